// round 12
// baseline (speedup 1.0000x reference)
#include <cuda_runtime.h>
#include <cuda_bf16.h>
#include <cstdint>

// Problem constants
#define BB   16
#define LL   1024
#define HID  1024
#define NROW (BB * HID)
#define NF   308
#define F0   205
#define TOPK 6

// ---------------- scratch (device globals) ----------------------------------
__device__ float  g_q[NROW * LL];        // (B,HID,L)
__device__ float  g_k[NROW * LL];
__device__ float  g_v[NROW * LL];
__device__ float  g_hidden[NROW * LL];   // (B*L, HID) row-major
__device__ __nv_bfloat16 g_x_hi[NROW * LL];    // x split, (B*L, HID)
__device__ __nv_bfloat16 g_x_lo[NROW * LL];
__device__ __nv_bfloat16 g_wt_hi[4 * HID * HID];  // transposed weights [n][k]
__device__ __nv_bfloat16 g_wt_lo[4 * HID * HID];
__device__ __nv_bfloat16 g_ctx_hi[NROW * LL];     // ctx (B*L, HID)
__device__ __nv_bfloat16 g_ctx_lo[NROW * LL];
__device__ float2 g_P[NROW * NF];
__device__ float2 g_S[BB][NF];
__device__ float  g_mv[BB][LL];
__device__ int    g_idx[TOPK];
__device__ float  g_tc[BB][TOPK];
__device__ float2 g_twG[1024];           // e^{-2*pi*i*j/1024}

// ---------------- twiddle init ----------------------------------------------
__global__ void __launch_bounds__(256) tw_init_kernel()
{
    int j = blockIdx.x * 256 + threadIdx.x;
    float s, c;
    sincospif(-(float)j / 512.0f, &s, &c);
    g_twG[j] = make_float2(c, s);
}

// ---------------- split helpers ---------------------------------------------
__device__ __forceinline__ void split1(float x, __nv_bfloat16& h, __nv_bfloat16& l) {
    h = __float2bfloat16(x);
    l = __float2bfloat16(x - __bfloat162float(h));
}

// x -> bf16 hi/lo (done once; feeds all 3 QKV GEMMs)
__global__ void __launch_bounds__(256) split_x_kernel(const float* __restrict__ x)
{
    size_t i = ((size_t)blockIdx.x * 256 + threadIdx.x) * 4;
    float4 v = *(const float4*)&x[i];
    __nv_bfloat16 h0, l0, h1, l1, h2, l2, h3, l3;
    split1(v.x, h0, l0); split1(v.y, h1, l1);
    split1(v.z, h2, l2); split1(v.w, h3, l3);
    __nv_bfloat162 hh01 = {h0, h1}, hh23 = {h2, h3};
    __nv_bfloat162 ll01 = {l0, l1}, ll23 = {l2, l3};
    uint2 hi, lo;
    hi.x = *(unsigned*)&hh01; hi.y = *(unsigned*)&hh23;
    lo.x = *(unsigned*)&ll01; lo.y = *(unsigned*)&ll23;
    *(uint2*)&g_x_hi[i] = hi;
    *(uint2*)&g_x_lo[i] = lo;
}

// ---------------- weight transpose + split ----------------------------------
__global__ void __launch_bounds__(256) transpose_w(
    const float* __restrict__ W0, const float* __restrict__ W1,
    const float* __restrict__ W2, const float* __restrict__ W3)
{
    __shared__ float tile[32][33];
    const float* src = (blockIdx.z == 0) ? W0 : (blockIdx.z == 1) ? W1
                     : (blockIdx.z == 2) ? W2 : W3;
    __nv_bfloat16* dh = g_wt_hi + (size_t)blockIdx.z * HID * HID;
    __nv_bfloat16* dl = g_wt_lo + (size_t)blockIdx.z * HID * HID;
    const int tx = threadIdx.x & 31, ty = threadIdx.x >> 5;   // 32 x 8
    const int x  = blockIdx.x * 32 + tx;
    const int y0 = blockIdx.y * 32;
    #pragma unroll
    for (int j = 0; j < 32; j += 8)
        tile[ty + j][tx] = src[(size_t)(y0 + ty + j) * HID + x];
    __syncthreads();
    const int x2 = y0 + tx;
    const int y2 = blockIdx.x * 32;
    #pragma unroll
    for (int j = 0; j < 32; j += 8) {
        float v = tile[tx][ty + j];
        __nv_bfloat16 h, l;
        split1(v, h, l);
        dh[(size_t)(y2 + ty + j) * HID + x2] = h;
        dl[(size_t)(y2 + ty + j) * HID + x2] = l;
    }
}

// ---------------- bf16-split GEMM, cp.async 3-stage pipeline ----------------
// smem per stage: 4 arrays (Ahi, Alo, Bhi, Blo), each 128 rows x 64B,
// 16B chunks XOR-swizzled: chunk' = chunk ^ ((row>>1)&3)
#define ARRB   8192                   // 128 * 64
#define STAGEB (4 * ARRB)             // 32768
#define GSMEM  (3 * STAGEB)           // 98304 (also >= 128*132*4 epilogue stage)

__device__ __forceinline__ void mma_bf16(float* c, const unsigned* a, const unsigned* b) {
    asm volatile(
        "mma.sync.aligned.m16n8k16.row.col.f32.bf16.bf16.f32 "
        "{%0,%1,%2,%3}, {%4,%5,%6,%7}, {%8,%9}, {%0,%1,%2,%3};"
        : "+f"(c[0]), "+f"(c[1]), "+f"(c[2]), "+f"(c[3])
        : "r"(a[0]), "r"(a[1]), "r"(a[2]), "r"(a[3]), "r"(b[0]), "r"(b[1]));
}
__device__ __forceinline__ void ldsm4(unsigned* r, uint32_t addr) {
    asm volatile("ldmatrix.sync.aligned.m8n8.x4.shared.b16 {%0,%1,%2,%3}, [%4];"
        : "=r"(r[0]), "=r"(r[1]), "=r"(r[2]), "=r"(r[3]) : "r"(addr));
}
__device__ __forceinline__ void cpasync16(uint32_t dst, const void* src) {
    asm volatile("cp.async.cg.shared.global [%0], [%1], 16;" :: "r"(dst), "l"(src));
}

__device__ __forceinline__ void issue_stage(
    uint32_t sb,
    const __nv_bfloat16* __restrict__ Ah, const __nv_bfloat16* __restrict__ Al,
    const __nv_bfloat16* __restrict__ Bh, const __nv_bfloat16* __restrict__ Bl,
    int m0, int n0, int k0, int tid)
{
    #pragma unroll
    for (int c = 0; c < 2; c++) {
        int chunk = tid + c * 256;
        int row = chunk >> 2, ch = chunk & 3;
        uint32_t so = (uint32_t)row * 64 + (uint32_t)((ch ^ ((row >> 1) & 3)) << 4);
        size_t ga = (size_t)(m0 + row) * 1024 + k0 + ch * 8;
        size_t gb = (size_t)(n0 + row) * 1024 + k0 + ch * 8;
        cpasync16(sb + so,            Ah + ga);
        cpasync16(sb + ARRB + so,     Al + ga);
        cpasync16(sb + 2 * ARRB + so, Bh + gb);
        cpasync16(sb + 3 * ARRB + so, Bl + gb);
    }
}

// mode 0: fused QK (which = blockIdx.z: 0,1); mode 2: V; mode 3: out proj
__global__ void __launch_bounds__(256, 2) gemm_bf16(
    const float* __restrict__ b0p, const float* __restrict__ b1p,
    const float* __restrict__ b2p, int mode)
{
    extern __shared__ char smem[];
    const uint32_t sbase = (uint32_t)__cvta_generic_to_shared(smem);

    const int which = (mode == 0) ? (int)blockIdx.z : mode;
    const float* bias = (which == 0) ? b0p : (which == 1) ? b1p : (which == 2) ? b2p : b0p;
    const __nv_bfloat16* Ah = (which == 3) ? g_ctx_hi : g_x_hi;
    const __nv_bfloat16* Al = (which == 3) ? g_ctx_lo : g_x_lo;
    const __nv_bfloat16* Bh = g_wt_hi + (size_t)which * HID * HID;
    const __nv_bfloat16* Bl = g_wt_lo + (size_t)which * HID * HID;
    float* Out = (which == 0) ? g_q : (which == 1) ? g_k
               : (which == 2) ? g_v : g_hidden;

    const int m0 = blockIdx.y * 128;
    const int n0 = blockIdx.x * 128;
    const int tid  = threadIdx.x;
    const int lane = tid & 31;
    const int wid  = tid >> 5;
    const int wm = wid & 1;
    const int wn = wid >> 1;
    const int gid = lane >> 2;
    const int tig = lane & 3;

    // ldmatrix per-lane bases
    const int a_rowb = wm * 64 + ((lane >> 3) & 1) * 8 + (lane & 7);  // + mi*16
    const int a_cbit = (lane >> 4) & 1;
    const int b_rowb = wn * 32 + ((lane >> 4) & 1) * 8 + (lane & 7);  // + pi*16
    const int b_cbit = (lane >> 3) & 1;

    uint32_t a_rb[4], b_rb[2];
    int a_swz[4], b_swz[2];
    #pragma unroll
    for (int mi = 0; mi < 4; mi++) {
        int r = a_rowb + mi * 16;
        a_rb[mi] = (uint32_t)r * 64;
        a_swz[mi] = (r >> 1) & 3;
    }
    #pragma unroll
    for (int pi = 0; pi < 2; pi++) {
        int r = b_rowb + pi * 16;
        b_rb[pi] = (uint32_t)r * 64;
        b_swz[pi] = (r >> 1) & 3;
    }

    float c[4][4][4];
    #pragma unroll
    for (int i = 0; i < 4; i++)
        #pragma unroll
        for (int j = 0; j < 4; j++)
            #pragma unroll
            for (int r = 0; r < 4; r++) c[i][j][r] = 0.f;

    // prologue: prefetch stages 0..1
    issue_stage(sbase + 0 * STAGEB, Ah, Al, Bh, Bl, m0, n0, 0,  tid);
    asm volatile("cp.async.commit_group;");
    issue_stage(sbase + 1 * STAGEB, Ah, Al, Bh, Bl, m0, n0, 32, tid);
    asm volatile("cp.async.commit_group;");

    int buf = 0, nbuf = 2;
    for (int kt = 0; kt < 32; kt++) {
        asm volatile("cp.async.wait_group 1;");
        __syncthreads();

        if (kt + 2 < 32)
            issue_stage(sbase + (uint32_t)nbuf * STAGEB, Ah, Al, Bh, Bl,
                        m0, n0, (kt + 2) * 32, tid);
        asm volatile("cp.async.commit_group;");

        const uint32_t sb = sbase + (uint32_t)buf * STAGEB;
        #pragma unroll
        for (int ks = 0; ks < 2; ks++) {
            unsigned ah[4][4], al[4][4], bh[4][2], bl[4][2];
            const int cbase = ks * 2;
            #pragma unroll
            for (int mi = 0; mi < 4; mi++) {
                uint32_t ad = sb + a_rb[mi]
                            + (uint32_t)((((cbase | a_cbit) ^ a_swz[mi]) << 4));
                ldsm4(ah[mi], ad);
                ldsm4(al[mi], ad + ARRB);
            }
            #pragma unroll
            for (int pi = 0; pi < 2; pi++) {
                uint32_t bd = sb + 2 * ARRB + b_rb[pi]
                            + (uint32_t)((((cbase | b_cbit) ^ b_swz[pi]) << 4));
                unsigned tmp[4];
                ldsm4(tmp, bd);
                bh[2 * pi][0] = tmp[0]; bh[2 * pi][1] = tmp[1];
                bh[2 * pi + 1][0] = tmp[2]; bh[2 * pi + 1][1] = tmp[3];
                ldsm4(tmp, bd + ARRB);
                bl[2 * pi][0] = tmp[0]; bl[2 * pi][1] = tmp[1];
                bl[2 * pi + 1][0] = tmp[2]; bl[2 * pi + 1][1] = tmp[3];
            }
            #pragma unroll
            for (int mi = 0; mi < 4; mi++)
                #pragma unroll
                for (int ni = 0; ni < 4; ni++) {
                    mma_bf16(c[mi][ni], ah[mi], bh[ni]);
                    mma_bf16(c[mi][ni], ah[mi], bl[ni]);
                    mma_bf16(c[mi][ni], al[mi], bh[ni]);
                }
        }
        buf = (buf == 2) ? 0 : buf + 1;
        nbuf = (nbuf == 2) ? 0 : nbuf + 1;
    }

    // epilogue
    if (which < 3) {
        // stage C into smem [n][m] (stride 132), then coalesced stores along t
        float* sf = (float*)smem;
        asm volatile("cp.async.wait_group 0;");
        __syncthreads();
        #pragma unroll
        for (int mi = 0; mi < 4; mi++) {
            #pragma unroll
            for (int r = 0; r < 2; r++) {
                int ml = wm * 64 + mi * 16 + gid + r * 8;
                #pragma unroll
                for (int ni = 0; ni < 4; ni++) {
                    int nl = wn * 32 + ni * 8 + 2 * tig;
                    sf[nl * 132 + ml]       = c[mi][ni][r * 2 + 0] + bias[n0 + nl];
                    sf[(nl + 1) * 132 + ml] = c[mi][ni][r * 2 + 1] + bias[n0 + nl + 1];
                }
            }
        }
        __syncthreads();
        const int bidx = m0 >> 10;
        const int t0 = m0 & 1023;
        #pragma unroll
        for (int it = 0; it < 16; it++) {
            int idx4 = it * 256 + tid;
            int ml4 = idx4 & 31, nl = idx4 >> 5;
            float4 v = *(float4*)&sf[nl * 132 + ml4 * 4];
            *(float4*)&Out[(((size_t)((bidx << 10) + n0 + nl)) << 10) + t0 + ml4 * 4] = v;
        }
    } else {
        #pragma unroll
        for (int mi = 0; mi < 4; mi++) {
            #pragma unroll
            for (int r = 0; r < 2; r++) {
                int m = m0 + wm * 64 + mi * 16 + gid + r * 8;
                #pragma unroll
                for (int ni = 0; ni < 4; ni++) {
                    int nb = n0 + wn * 32 + ni * 8 + 2 * tig;
                    float2 v;
                    v.x = c[mi][ni][r * 2 + 0] + bias[nb];
                    v.y = c[mi][ni][r * 2 + 1] + bias[nb + 1];
                    *(float2*)&Out[(size_t)m * 1024 + nb] = v;
                }
            }
        }
    }
}

// ---------------- radix-4 DIF FFT + cross spectrum --------------------------
__device__ __forceinline__ int fswz(int p) { return p ^ ((p >> 2) & 15); }
__device__ __forceinline__ int rev4(int x) {
    return ((x & 3) << 8) | (((x >> 2) & 3) << 6) | (((x >> 4) & 3) << 4)
         | (((x >> 6) & 3) << 2) | ((x >> 8) & 3);
}
__device__ __forceinline__ float2 cmul(float2 a, float2 w) {
    return make_float2(a.x * w.x - a.y * w.y, a.x * w.y + a.y * w.x);
}

__global__ void __launch_bounds__(256) fft_corr_kernel()
{
    __shared__ float2 Zs[1024];
    __shared__ float2 tw[1024];
    const int row = blockIdx.x;
    const int t = threadIdx.x;
    const float* qr = g_q + (size_t)row * 1024;
    const float* kr = g_k + (size_t)row * 1024;

    for (int j = t; j < 1024; j += 256) tw[j] = g_twG[j];
    __syncthreads();

    {
        float2 x0 = make_float2(qr[t],       kr[t]);
        float2 x1 = make_float2(qr[t + 256], kr[t + 256]);
        float2 x2 = make_float2(qr[t + 512], kr[t + 512]);
        float2 x3 = make_float2(qr[t + 768], kr[t + 768]);
        float2 p02 = make_float2(x0.x + x2.x, x0.y + x2.y);
        float2 m02 = make_float2(x0.x - x2.x, x0.y - x2.y);
        float2 p13 = make_float2(x1.x + x3.x, x1.y + x3.y);
        float2 m13 = make_float2(x1.x - x3.x, x1.y - x3.y);
        float2 y0 = make_float2(p02.x + p13.x, p02.y + p13.y);
        float2 y2 = make_float2(p02.x - p13.x, p02.y - p13.y);
        float2 y1 = make_float2(m02.x + m13.y, m02.y - m13.x);
        float2 y3 = make_float2(m02.x - m13.y, m02.y + m13.x);
        int e = t;
        Zs[fswz(t)]       = y0;
        Zs[fswz(t + 256)] = cmul(y1, tw[e]);
        Zs[fswz(t + 512)] = cmul(y2, tw[2 * e]);
        Zs[fswz(t + 768)] = cmul(y3, tw[3 * e]);
    }
    __syncthreads();

    #pragma unroll
    for (int s = 1; s < 5; s++) {
        const int qsh = 8 - 2 * s;
        const int quarter = 1 << qsh;
        const int j = t & (quarter - 1);
        const int i0 = ((t >> qsh) << (qsh + 2)) + j;
        const int e = j << (2 * s);
        float2 x0 = Zs[fswz(i0)];
        float2 x1 = Zs[fswz(i0 + quarter)];
        float2 x2 = Zs[fswz(i0 + 2 * quarter)];
        float2 x3 = Zs[fswz(i0 + 3 * quarter)];
        float2 p02 = make_float2(x0.x + x2.x, x0.y + x2.y);
        float2 m02 = make_float2(x0.x - x2.x, x0.y - x2.y);
        float2 p13 = make_float2(x1.x + x3.x, x1.y + x3.y);
        float2 m13 = make_float2(x1.x - x3.x, x1.y - x3.y);
        float2 y0 = make_float2(p02.x + p13.x, p02.y + p13.y);
        float2 y2 = make_float2(p02.x - p13.x, p02.y - p13.y);
        float2 y1 = make_float2(m02.x + m13.y, m02.y - m13.x);
        float2 y3 = make_float2(m02.x - m13.y, m02.y + m13.x);
        __syncthreads();
        Zs[fswz(i0)]               = y0;
        Zs[fswz(i0 + quarter)]     = cmul(y1, tw[e]);
        Zs[fswz(i0 + 2 * quarter)] = cmul(y2, tw[2 * e]);
        Zs[fswz(i0 + 3 * quarter)] = cmul(y3, tw[3 * e]);
        __syncthreads();
    }

    for (int f = F0 + t; f <= 512; f += 256) {
        float2 A  = Zs[fswz(rev4(f))];
        float2 Zc = Zs[fswz(rev4(1024 - f))];
        float Br =  Zc.x, Bi = -Zc.y;
        float Ur = A.x + Br, Ui = A.y + Bi;
        float Vr = A.x - Br, Vi = A.y - Bi;
        float Pr = 0.25f * (Ur * Vi - Ui * Vr);
        float Pi = 0.25f * (Ur * Vr + Ui * Vi);
        g_P[(size_t)row * NF + (f - F0)] = make_float2(Pr, Pi);
    }
}

// ---------------- deterministic channel reduction (coalesced) ---------------
// grid (BB, 77): each block sums 4 consecutive freqs over 1024 channels.
// 4-lane groups read aligned 32B sectors (row stride 2464 = 77*32).
__global__ void __launch_bounds__(256) reduce_S_kernel()
{
    const int b = blockIdx.x;
    const int tid = threadIdx.x;
    const int j = blockIdx.y * 4 + (tid & 3);
    float2 acc = make_float2(0.f, 0.f);
    for (int r = tid >> 2; r < 1024; r += 64) {
        float2 p = g_P[(size_t)((b << 10) + r) * NF + j];
        acc.x += p.x; acc.y += p.y;
    }
    __shared__ float2 sh[256];
    sh[tid] = acc;
    __syncthreads();
    for (int o = 128; o >= 4; o >>= 1) {
        if (tid < o) { sh[tid].x += sh[tid + o].x; sh[tid].y += sh[tid + o].y; }
        __syncthreads();
    }
    if (tid < 4) g_S[b][blockIdx.y * 4 + tid] = sh[tid];
}

// ---------------- irfft of masked spectrum -> mean_value --------------------
__global__ void __launch_bounds__(256) irfft_mean_kernel()
{
    __shared__ float2 tw[1024];
    __shared__ float2 Sb[NF];
    const int b = blockIdx.x;
    const int tid = threadIdx.x;
    for (int j = tid; j < 1024; j += 256) {
        float2 w = g_twG[j];                 // e^{-...}; conj -> e^{+...}
        tw[j] = make_float2(w.x, -w.y);
    }
    for (int j = tid; j < NF; j += 256) Sb[j] = g_S[b][j];
    __syncthreads();

    const int tau = blockIdx.y * 256 + tid;
    float acc = 0.f;
    #pragma unroll 4
    for (int j = 0; j < NF - 1; j++) {
        int id = ((F0 + j) * tau) & 1023;
        float2 s = Sb[j], w = tw[id];
        acc += s.x * w.x - s.y * w.y;
    }
    acc *= 2.0f;
    {
        int id = (512 * tau) & 1023;
        float2 s = Sb[NF - 1], w = tw[id];
        acc += s.x * w.x - s.y * w.y;
    }
    g_mv[b][tau] = acc * (1.0f / (1024.0f * 1024.0f));
}

// ---------------- global top-6 lags + per-batch softmax ---------------------
__global__ void __launch_bounds__(256) topk_kernel()
{
    __shared__ float g[1024];
    __shared__ float rv[256];
    __shared__ int   ri[256];
    __shared__ int   chosen[TOPK];
    const int tid = threadIdx.x;

    for (int t = tid; t < 1024; t += 256) {
        float s = 0.f;
        #pragma unroll
        for (int b = 0; b < BB; b++) s += g_mv[b][t];
        g[t] = s;
    }
    __syncthreads();

    for (int p = 0; p < TOPK; p++) {
        float best = -3.0e38f; int bi = 1 << 30;
        for (int t = tid; t < 1024; t += 256) {
            float v = g[t];
            if (v > best) { best = v; bi = t; }
        }
        rv[tid] = best; ri[tid] = bi;
        __syncthreads();
        for (int o = 128; o > 0; o >>= 1) {
            if (tid < o) {
                float v2 = rv[tid + o]; int i2 = ri[tid + o];
                if (v2 > rv[tid] || (v2 == rv[tid] && i2 < ri[tid])) {
                    rv[tid] = v2; ri[tid] = i2;
                }
            }
            __syncthreads();
        }
        if (tid == 0) { chosen[p] = ri[0]; g[ri[0]] = -3.0e38f; }
        __syncthreads();
    }

    if (tid < BB) {
        int b = tid;
        float w[TOPK], mx = -3.0e38f;
        #pragma unroll
        for (int i = 0; i < TOPK; i++) { w[i] = g_mv[b][chosen[i]]; mx = fmaxf(mx, w[i]); }
        float sum = 0.f;
        #pragma unroll
        for (int i = 0; i < TOPK; i++) { w[i] = expf(w[i] - mx); sum += w[i]; }
        #pragma unroll
        for (int i = 0; i < TOPK; i++) g_tc[b][i] = w[i] / sum;
    }
    if (tid >= 32 && tid < 32 + TOPK) g_idx[tid - 32] = chosen[tid - 32];
}

// ---------------- fused shift-agg + transpose + bf16 split ------------------
#define GT_SMEM (32 * 1025 * 4)
__global__ void __launch_bounds__(256) gatherT_kernel()
{
    extern __shared__ float vs[];            // [32][1025]
    __shared__ int   sh[TOPK];
    __shared__ float w[TOPK];
    const int b  = blockIdx.y;
    const int c0 = blockIdx.x * 32;
    const int tid = threadIdx.x;
    if (tid < TOPK) { sh[tid] = g_idx[tid]; w[tid] = g_tc[b][tid]; }
    for (int idx = tid; idx < 32 * 1024; idx += 256) {
        int r = idx >> 10, t = idx & 1023;
        vs[r * 1025 + t] = g_v[((size_t)(b << 10) + c0 + r) * 1024 + t];
    }
    __syncthreads();
    const int cc = tid & 31;
    for (int tt = tid >> 5; tt < 1024; tt += 8) {
        float a = 0.f;
        #pragma unroll
        for (int i = 0; i < TOPK; i++)
            a += w[i] * vs[cc * 1025 + ((tt + sh[i]) & 1023)];
        size_t pos = ((size_t)(b << 10) + tt) * 1024 + c0 + cc;
        __nv_bfloat16 h, l;
        split1(a, h, l);
        g_ctx_hi[pos] = h;
        g_ctx_lo[pos] = l;
    }
}

// ---------------- residual + LayerNorm --------------------------------------
__global__ void __launch_bounds__(256) ln_kernel(
    const float* __restrict__ x, const float* __restrict__ gamma,
    const float* __restrict__ beta, float* __restrict__ out)
{
    const int m = blockIdx.x;
    const int tid = threadIdx.x;
    const float* h  = g_hidden + (size_t)m * 1024;
    const float* xi = x        + (size_t)m * 1024;

    float v[4];
    float s1 = 0.f, s2 = 0.f;
    #pragma unroll
    for (int i = 0; i < 4; i++) {
        float t = h[tid + 256 * i] + xi[tid + 256 * i];
        v[i] = t; s1 += t; s2 += t * t;
    }
    #pragma unroll
    for (int o = 16; o > 0; o >>= 1) {
        s1 += __shfl_xor_sync(0xffffffffu, s1, o);
        s2 += __shfl_xor_sync(0xffffffffu, s2, o);
    }
    __shared__ float w1[8], w2[8];
    __shared__ float sh_mean, sh_inv;
    const int wid = tid >> 5, lane = tid & 31;
    if (lane == 0) { w1[wid] = s1; w2[wid] = s2; }
    __syncthreads();
    if (tid == 0) {
        float a = 0.f, bq = 0.f;
        #pragma unroll
        for (int i = 0; i < 8; i++) { a += w1[i]; bq += w2[i]; }
        float mean = a * (1.0f / 1024.0f);
        float var  = bq * (1.0f / 1024.0f) - mean * mean;
        sh_mean = mean;
        sh_inv  = rsqrtf(var + 1e-12f);
    }
    __syncthreads();
    const float mean = sh_mean, inv = sh_inv;
    #pragma unroll
    for (int i = 0; i < 4; i++) {
        int c = tid + 256 * i;
        out[(size_t)m * 1024 + c] = (v[i] - mean) * inv * gamma[c] + beta[c];
    }
}

// ---------------- launch ----------------------------------------------------
extern "C" void kernel_launch(void* const* d_in, const int* in_sizes, int n_in,
                              void* d_out, int out_size)
{
    (void)in_sizes; (void)n_in; (void)out_size;
    const float* x     = (const float*)d_in[0];
    const float* Wq    = (const float*)d_in[2];
    const float* bq    = (const float*)d_in[3];
    const float* Wk    = (const float*)d_in[4];
    const float* bk    = (const float*)d_in[5];
    const float* Wv    = (const float*)d_in[6];
    const float* bv    = (const float*)d_in[7];
    const float* Wd    = (const float*)d_in[8];
    const float* bd    = (const float*)d_in[9];
    const float* gamma = (const float*)d_in[10];
    const float* beta  = (const float*)d_in[11];
    float* out = (float*)d_out;

    static cudaStream_t s2 = nullptr;
    static cudaEvent_t ev0 = nullptr, evT = nullptr, evQK = nullptr, evV = nullptr;
    static bool attr_done = false;
    if (!attr_done) {
        cudaFuncSetAttribute(gemm_bf16,      cudaFuncAttributeMaxDynamicSharedMemorySize, GSMEM);
        cudaFuncSetAttribute(gatherT_kernel, cudaFuncAttributeMaxDynamicSharedMemorySize, GT_SMEM);
        cudaStreamCreateWithFlags(&s2, cudaStreamNonBlocking);
        cudaEventCreateWithFlags(&ev0,  cudaEventDisableTiming);
        cudaEventCreateWithFlags(&evT,  cudaEventDisableTiming);
        cudaEventCreateWithFlags(&evQK, cudaEventDisableTiming);
        cudaEventCreateWithFlags(&evV,  cudaEventDisableTiming);
        attr_done = true;
    }

    // fork: twiddles + weight transpose on s2 concurrent with split_x on main
    cudaEventRecord(ev0, 0);
    cudaStreamWaitEvent(s2, ev0, 0);
    tw_init_kernel<<<4, 256, 0, s2>>>();
    transpose_w<<<dim3(32, 32, 4), 256, 0, s2>>>(Wq, Wk, Wv, Wd);
    split_x_kernel<<<NROW * LL / 1024, 256>>>(x);
    cudaEventRecord(evT, s2);
    cudaStreamWaitEvent(0, evT, 0);

    // Q,K GEMM on main stream
    gemm_bf16<<<dim3(8, 128, 2), 256, GSMEM>>>(bq, bk, bv, 0);
    cudaEventRecord(evQK, 0);

    // V GEMM on s2, concurrent with the FFT chain on main
    cudaStreamWaitEvent(s2, evQK, 0);
    gemm_bf16<<<dim3(8, 128, 1), 256, GSMEM, s2>>>(bq, bk, bv, 2);
    cudaEventRecord(evV, s2);

    fft_corr_kernel<<<NROW, 256>>>();
    reduce_S_kernel<<<dim3(BB, 77), 256>>>();
    irfft_mean_kernel<<<dim3(BB, 4), 256>>>();
    topk_kernel<<<1, 256>>>();

    // join: gatherT needs both topk (main) and v (s2)
    cudaStreamWaitEvent(0, evV, 0);
    gatherT_kernel<<<dim3(32, BB), 256, GT_SMEM>>>();
    gemm_bf16<<<dim3(8, 128, 1), 256, GSMEM>>>(bd, bd, bd, 3);
    ln_kernel<<<NROW, 256>>>(x, gamma, beta, out);
}

// round 13
// speedup vs baseline: 1.1590x; 1.1590x over previous
#include <cuda_runtime.h>
#include <cuda_bf16.h>
#include <cstdint>

// Problem constants
#define BB   16
#define LL   1024
#define HID  1024
#define NROW (BB * HID)
#define NF   308
#define F0   205
#define TOPK 6

// ---------------- scratch (device globals) ----------------------------------
__device__ float  g_q[NROW * LL];        // (B,HID,L)
__device__ float  g_k[NROW * LL];
__device__ float  g_hidden[NROW * LL];   // hv = v@Wd, (B*L, HID) row-major
__device__ __nv_bfloat16 g_x_hi[NROW * LL];    // x split, (B*L, HID)
__device__ __nv_bfloat16 g_x_lo[NROW * LL];
__device__ __nv_bfloat16 g_wt_hi[4 * HID * HID];  // transposed weights [n][k]
__device__ __nv_bfloat16 g_wt_lo[4 * HID * HID];
__device__ __nv_bfloat16 g_v_hi[NROW * LL];       // v (B*L, HID) split
__device__ __nv_bfloat16 g_v_lo[NROW * LL];
__device__ float2 g_P[NROW * NF];
__device__ float2 g_S[BB][NF];
__device__ float  g_mv[BB][LL];
__device__ int    g_idx[TOPK];
__device__ float  g_tc[BB][TOPK];
__device__ float2 g_twG[1024];           // e^{-2*pi*i*j/1024}

// ---------------- twiddle init ----------------------------------------------
__global__ void __launch_bounds__(256) tw_init_kernel()
{
    int j = blockIdx.x * 256 + threadIdx.x;
    float s, c;
    sincospif(-(float)j / 512.0f, &s, &c);
    g_twG[j] = make_float2(c, s);
}

// ---------------- split helpers ---------------------------------------------
__device__ __forceinline__ void split1(float x, __nv_bfloat16& h, __nv_bfloat16& l) {
    h = __float2bfloat16(x);
    l = __float2bfloat16(x - __bfloat162float(h));
}

// x -> bf16 hi/lo (done once; feeds all 3 QKV GEMMs)
__global__ void __launch_bounds__(256) split_x_kernel(const float* __restrict__ x)
{
    size_t i = ((size_t)blockIdx.x * 256 + threadIdx.x) * 4;
    float4 v = *(const float4*)&x[i];
    __nv_bfloat16 h0, l0, h1, l1, h2, l2, h3, l3;
    split1(v.x, h0, l0); split1(v.y, h1, l1);
    split1(v.z, h2, l2); split1(v.w, h3, l3);
    __nv_bfloat162 hh01 = {h0, h1}, hh23 = {h2, h3};
    __nv_bfloat162 ll01 = {l0, l1}, ll23 = {l2, l3};
    uint2 hi, lo;
    hi.x = *(unsigned*)&hh01; hi.y = *(unsigned*)&hh23;
    lo.x = *(unsigned*)&ll01; lo.y = *(unsigned*)&ll23;
    *(uint2*)&g_x_hi[i] = hi;
    *(uint2*)&g_x_lo[i] = lo;
}

// ---------------- weight transpose + split ----------------------------------
__global__ void __launch_bounds__(256) transpose_w(
    const float* __restrict__ W0, const float* __restrict__ W1,
    const float* __restrict__ W2, const float* __restrict__ W3)
{
    __shared__ float tile[32][33];
    const float* src = (blockIdx.z == 0) ? W0 : (blockIdx.z == 1) ? W1
                     : (blockIdx.z == 2) ? W2 : W3;
    __nv_bfloat16* dh = g_wt_hi + (size_t)blockIdx.z * HID * HID;
    __nv_bfloat16* dl = g_wt_lo + (size_t)blockIdx.z * HID * HID;
    const int tx = threadIdx.x & 31, ty = threadIdx.x >> 5;   // 32 x 8
    const int x  = blockIdx.x * 32 + tx;
    const int y0 = blockIdx.y * 32;
    #pragma unroll
    for (int j = 0; j < 32; j += 8)
        tile[ty + j][tx] = src[(size_t)(y0 + ty + j) * HID + x];
    __syncthreads();
    const int x2 = y0 + tx;
    const int y2 = blockIdx.x * 32;
    #pragma unroll
    for (int j = 0; j < 32; j += 8) {
        float v = tile[tx][ty + j];
        __nv_bfloat16 h, l;
        split1(v, h, l);
        dh[(size_t)(y2 + ty + j) * HID + x2] = h;
        dl[(size_t)(y2 + ty + j) * HID + x2] = l;
    }
}

// ---------------- bf16-split GEMM, cp.async 3-stage pipeline ----------------
// smem per stage: 4 arrays (Ahi, Alo, Bhi, Blo), each 128 rows x 64B,
// 16B chunks XOR-swizzled: chunk' = chunk ^ ((row>>1)&3)
#define ARRB   8192                   // 128 * 64
#define STAGEB (4 * ARRB)             // 32768
#define GSMEM  (3 * STAGEB)           // 98304

__device__ __forceinline__ void mma_bf16(float* c, const unsigned* a, const unsigned* b) {
    asm volatile(
        "mma.sync.aligned.m16n8k16.row.col.f32.bf16.bf16.f32 "
        "{%0,%1,%2,%3}, {%4,%5,%6,%7}, {%8,%9}, {%0,%1,%2,%3};"
        : "+f"(c[0]), "+f"(c[1]), "+f"(c[2]), "+f"(c[3])
        : "r"(a[0]), "r"(a[1]), "r"(a[2]), "r"(a[3]), "r"(b[0]), "r"(b[1]));
}
__device__ __forceinline__ void ldsm4(unsigned* r, uint32_t addr) {
    asm volatile("ldmatrix.sync.aligned.m8n8.x4.shared.b16 {%0,%1,%2,%3}, [%4];"
        : "=r"(r[0]), "=r"(r[1]), "=r"(r[2]), "=r"(r[3]) : "r"(addr));
}
__device__ __forceinline__ void cpasync16(uint32_t dst, const void* src) {
    asm volatile("cp.async.cg.shared.global [%0], [%1], 16;" :: "r"(dst), "l"(src));
}

__device__ __forceinline__ void issue_stage(
    uint32_t sb,
    const __nv_bfloat16* __restrict__ Ah, const __nv_bfloat16* __restrict__ Al,
    const __nv_bfloat16* __restrict__ Bh, const __nv_bfloat16* __restrict__ Bl,
    int m0, int n0, int k0, int tid)
{
    #pragma unroll
    for (int c = 0; c < 2; c++) {
        int chunk = tid + c * 256;
        int row = chunk >> 2, ch = chunk & 3;
        uint32_t so = (uint32_t)row * 64 + (uint32_t)((ch ^ ((row >> 1) & 3)) << 4);
        size_t ga = (size_t)(m0 + row) * 1024 + k0 + ch * 8;
        size_t gb = (size_t)(n0 + row) * 1024 + k0 + ch * 8;
        cpasync16(sb + so,            Ah + ga);
        cpasync16(sb + ARRB + so,     Al + ga);
        cpasync16(sb + 2 * ARRB + so, Bh + gb);
        cpasync16(sb + 3 * ARRB + so, Bl + gb);
    }
}

// mode 0: fused QK (which = blockIdx.z: 0=Q,1=K, scatter to (B,HID,L))
// mode 2: V -> split bf16 (B*L,HID) rows (+bias)
// mode 3: hv = v@Wd -> fp32 (B*L,HID) rows (no bias)
__global__ void __launch_bounds__(256, 2) gemm_bf16(
    const float* __restrict__ b0p, const float* __restrict__ b1p,
    const float* __restrict__ b2p, int mode)
{
    extern __shared__ char smem[];
    const uint32_t sbase = (uint32_t)__cvta_generic_to_shared(smem);

    const int which = (mode == 0) ? (int)blockIdx.z : mode;
    const float* bias = (which == 0) ? b0p : (which == 1) ? b1p : b2p;
    const __nv_bfloat16* Ah = (which == 3) ? g_v_hi : g_x_hi;
    const __nv_bfloat16* Al = (which == 3) ? g_v_lo : g_x_lo;
    const __nv_bfloat16* Bh = g_wt_hi + (size_t)which * HID * HID;
    const __nv_bfloat16* Bl = g_wt_lo + (size_t)which * HID * HID;

    const int m0 = blockIdx.y * 128;
    const int n0 = blockIdx.x * 128;
    const int tid  = threadIdx.x;
    const int lane = tid & 31;
    const int wid  = tid >> 5;
    const int wm = wid & 1;
    const int wn = wid >> 1;
    const int gid = lane >> 2;
    const int tig = lane & 3;

    // ldmatrix per-lane bases
    const int a_rowb = wm * 64 + ((lane >> 3) & 1) * 8 + (lane & 7);  // + mi*16
    const int a_cbit = (lane >> 4) & 1;
    const int b_rowb = wn * 32 + ((lane >> 4) & 1) * 8 + (lane & 7);  // + pi*16
    const int b_cbit = (lane >> 3) & 1;

    uint32_t a_rb[4], b_rb[2];
    int a_swz[4], b_swz[2];
    #pragma unroll
    for (int mi = 0; mi < 4; mi++) {
        int r = a_rowb + mi * 16;
        a_rb[mi] = (uint32_t)r * 64;
        a_swz[mi] = (r >> 1) & 3;
    }
    #pragma unroll
    for (int pi = 0; pi < 2; pi++) {
        int r = b_rowb + pi * 16;
        b_rb[pi] = (uint32_t)r * 64;
        b_swz[pi] = (r >> 1) & 3;
    }

    float c[4][4][4];
    #pragma unroll
    for (int i = 0; i < 4; i++)
        #pragma unroll
        for (int j = 0; j < 4; j++)
            #pragma unroll
            for (int r = 0; r < 4; r++) c[i][j][r] = 0.f;

    // prologue: prefetch stages 0..1
    issue_stage(sbase + 0 * STAGEB, Ah, Al, Bh, Bl, m0, n0, 0,  tid);
    asm volatile("cp.async.commit_group;");
    issue_stage(sbase + 1 * STAGEB, Ah, Al, Bh, Bl, m0, n0, 32, tid);
    asm volatile("cp.async.commit_group;");

    int buf = 0, nbuf = 2;
    for (int kt = 0; kt < 32; kt++) {
        asm volatile("cp.async.wait_group 1;");
        __syncthreads();

        if (kt + 2 < 32)
            issue_stage(sbase + (uint32_t)nbuf * STAGEB, Ah, Al, Bh, Bl,
                        m0, n0, (kt + 2) * 32, tid);
        asm volatile("cp.async.commit_group;");

        const uint32_t sb = sbase + (uint32_t)buf * STAGEB;
        #pragma unroll
        for (int ks = 0; ks < 2; ks++) {
            unsigned ah[4][4], al[4][4], bh[4][2], bl[4][2];
            const int cbase = ks * 2;
            #pragma unroll
            for (int mi = 0; mi < 4; mi++) {
                uint32_t ad = sb + a_rb[mi]
                            + (uint32_t)((((cbase | a_cbit) ^ a_swz[mi]) << 4));
                ldsm4(ah[mi], ad);
                ldsm4(al[mi], ad + ARRB);
            }
            #pragma unroll
            for (int pi = 0; pi < 2; pi++) {
                uint32_t bd = sb + 2 * ARRB + b_rb[pi]
                            + (uint32_t)((((cbase | b_cbit) ^ b_swz[pi]) << 4));
                unsigned tmp[4];
                ldsm4(tmp, bd);
                bh[2 * pi][0] = tmp[0]; bh[2 * pi][1] = tmp[1];
                bh[2 * pi + 1][0] = tmp[2]; bh[2 * pi + 1][1] = tmp[3];
                ldsm4(tmp, bd + ARRB);
                bl[2 * pi][0] = tmp[0]; bl[2 * pi][1] = tmp[1];
                bl[2 * pi + 1][0] = tmp[2]; bl[2 * pi + 1][1] = tmp[3];
            }
            #pragma unroll
            for (int mi = 0; mi < 4; mi++)
                #pragma unroll
                for (int ni = 0; ni < 4; ni++) {
                    mma_bf16(c[mi][ni], ah[mi], bh[ni]);
                    mma_bf16(c[mi][ni], ah[mi], bl[ni]);
                    mma_bf16(c[mi][ni], al[mi], bh[ni]);
                }
        }
        buf = (buf == 2) ? 0 : buf + 1;
        nbuf = (nbuf == 2) ? 0 : nbuf + 1;
    }

    // epilogue
    if (which < 2) {
        float* Out = (which == 0) ? g_q : g_k;
        const int bidx = m0 >> 10;
        #pragma unroll
        for (int mi = 0; mi < 4; mi++) {
            #pragma unroll
            for (int r = 0; r < 2; r++) {
                int m = m0 + wm * 64 + mi * 16 + gid + r * 8;
                int t = m & 1023;
                #pragma unroll
                for (int ni = 0; ni < 4; ni++) {
                    int nb = n0 + wn * 32 + ni * 8 + 2 * tig;
                    float v0 = c[mi][ni][r * 2 + 0] + bias[nb];
                    float v1 = c[mi][ni][r * 2 + 1] + bias[nb + 1];
                    Out[(((size_t)(bidx << 10) + nb) << 10) + t] = v0;
                    Out[(((size_t)(bidx << 10) + nb + 1) << 10) + t] = v1;
                }
            }
        }
    } else if (which == 2) {
        // v rows (B*L,HID): add bias, split to bf16 hi/lo
        #pragma unroll
        for (int mi = 0; mi < 4; mi++) {
            #pragma unroll
            for (int r = 0; r < 2; r++) {
                int m = m0 + wm * 64 + mi * 16 + gid + r * 8;
                #pragma unroll
                for (int ni = 0; ni < 4; ni++) {
                    int nb = n0 + wn * 32 + ni * 8 + 2 * tig;
                    float v0 = c[mi][ni][r * 2 + 0] + bias[nb];
                    float v1 = c[mi][ni][r * 2 + 1] + bias[nb + 1];
                    __nv_bfloat16 h0, l0, h1, l1;
                    split1(v0, h0, l0); split1(v1, h1, l1);
                    __nv_bfloat162 hh = {h0, h1}, ll = {l0, l1};
                    *(__nv_bfloat162*)&g_v_hi[(size_t)m * 1024 + nb] = hh;
                    *(__nv_bfloat162*)&g_v_lo[(size_t)m * 1024 + nb] = ll;
                }
            }
        }
    } else {
        // hv rows (B*L,HID), no bias
        #pragma unroll
        for (int mi = 0; mi < 4; mi++) {
            #pragma unroll
            for (int r = 0; r < 2; r++) {
                int m = m0 + wm * 64 + mi * 16 + gid + r * 8;
                #pragma unroll
                for (int ni = 0; ni < 4; ni++) {
                    int nb = n0 + wn * 32 + ni * 8 + 2 * tig;
                    float2 v;
                    v.x = c[mi][ni][r * 2 + 0];
                    v.y = c[mi][ni][r * 2 + 1];
                    *(float2*)&g_hidden[(size_t)m * 1024 + nb] = v;
                }
            }
        }
    }
}

// ---------------- radix-4 DIF FFT + cross spectrum --------------------------
__device__ __forceinline__ int fswz(int p) { return p ^ ((p >> 2) & 15); }
__device__ __forceinline__ int rev4(int x) {
    return ((x & 3) << 8) | (((x >> 2) & 3) << 6) | (((x >> 4) & 3) << 4)
         | (((x >> 6) & 3) << 2) | ((x >> 8) & 3);
}
__device__ __forceinline__ float2 cmul(float2 a, float2 w) {
    return make_float2(a.x * w.x - a.y * w.y, a.x * w.y + a.y * w.x);
}

__global__ void __launch_bounds__(256) fft_corr_kernel()
{
    __shared__ float2 Zs[1024];
    __shared__ float2 tw[1024];
    const int row = blockIdx.x;
    const int t = threadIdx.x;
    const float* qr = g_q + (size_t)row * 1024;
    const float* kr = g_k + (size_t)row * 1024;

    for (int j = t; j < 1024; j += 256) tw[j] = g_twG[j];
    __syncthreads();

    {
        float2 x0 = make_float2(qr[t],       kr[t]);
        float2 x1 = make_float2(qr[t + 256], kr[t + 256]);
        float2 x2 = make_float2(qr[t + 512], kr[t + 512]);
        float2 x3 = make_float2(qr[t + 768], kr[t + 768]);
        float2 p02 = make_float2(x0.x + x2.x, x0.y + x2.y);
        float2 m02 = make_float2(x0.x - x2.x, x0.y - x2.y);
        float2 p13 = make_float2(x1.x + x3.x, x1.y + x3.y);
        float2 m13 = make_float2(x1.x - x3.x, x1.y - x3.y);
        float2 y0 = make_float2(p02.x + p13.x, p02.y + p13.y);
        float2 y2 = make_float2(p02.x - p13.x, p02.y - p13.y);
        float2 y1 = make_float2(m02.x + m13.y, m02.y - m13.x);
        float2 y3 = make_float2(m02.x - m13.y, m02.y + m13.x);
        int e = t;
        Zs[fswz(t)]       = y0;
        Zs[fswz(t + 256)] = cmul(y1, tw[e]);
        Zs[fswz(t + 512)] = cmul(y2, tw[2 * e]);
        Zs[fswz(t + 768)] = cmul(y3, tw[3 * e]);
    }
    __syncthreads();

    #pragma unroll
    for (int s = 1; s < 5; s++) {
        const int qsh = 8 - 2 * s;
        const int quarter = 1 << qsh;
        const int j = t & (quarter - 1);
        const int i0 = ((t >> qsh) << (qsh + 2)) + j;
        const int e = j << (2 * s);
        float2 x0 = Zs[fswz(i0)];
        float2 x1 = Zs[fswz(i0 + quarter)];
        float2 x2 = Zs[fswz(i0 + 2 * quarter)];
        float2 x3 = Zs[fswz(i0 + 3 * quarter)];
        float2 p02 = make_float2(x0.x + x2.x, x0.y + x2.y);
        float2 m02 = make_float2(x0.x - x2.x, x0.y - x2.y);
        float2 p13 = make_float2(x1.x + x3.x, x1.y + x3.y);
        float2 m13 = make_float2(x1.x - x3.x, x1.y - x3.y);
        float2 y0 = make_float2(p02.x + p13.x, p02.y + p13.y);
        float2 y2 = make_float2(p02.x - p13.x, p02.y - p13.y);
        float2 y1 = make_float2(m02.x + m13.y, m02.y - m13.x);
        float2 y3 = make_float2(m02.x - m13.y, m02.y + m13.x);
        __syncthreads();
        Zs[fswz(i0)]               = y0;
        Zs[fswz(i0 + quarter)]     = cmul(y1, tw[e]);
        Zs[fswz(i0 + 2 * quarter)] = cmul(y2, tw[2 * e]);
        Zs[fswz(i0 + 3 * quarter)] = cmul(y3, tw[3 * e]);
        __syncthreads();
    }

    for (int f = F0 + t; f <= 512; f += 256) {
        float2 A  = Zs[fswz(rev4(f))];
        float2 Zc = Zs[fswz(rev4(1024 - f))];
        float Br =  Zc.x, Bi = -Zc.y;
        float Ur = A.x + Br, Ui = A.y + Bi;
        float Vr = A.x - Br, Vi = A.y - Bi;
        float Pr = 0.25f * (Ur * Vi - Ui * Vr);
        float Pi = 0.25f * (Ur * Vr + Ui * Vi);
        g_P[(size_t)row * NF + (f - F0)] = make_float2(Pr, Pi);
    }
}

// ---------------- deterministic channel reduction (coalesced) ---------------
__global__ void __launch_bounds__(256) reduce_S_kernel()
{
    const int b = blockIdx.x;
    const int tid = threadIdx.x;
    const int j = blockIdx.y * 4 + (tid & 3);
    float2 acc = make_float2(0.f, 0.f);
    for (int r = tid >> 2; r < 1024; r += 64) {
        float2 p = g_P[(size_t)((b << 10) + r) * NF + j];
        acc.x += p.x; acc.y += p.y;
    }
    __shared__ float2 sh[256];
    sh[tid] = acc;
    __syncthreads();
    for (int o = 128; o >= 4; o >>= 1) {
        if (tid < o) { sh[tid].x += sh[tid + o].x; sh[tid].y += sh[tid + o].y; }
        __syncthreads();
    }
    if (tid < 4) g_S[b][blockIdx.y * 4 + tid] = sh[tid];
}

// ---------------- irfft of masked spectrum -> mean_value --------------------
__global__ void __launch_bounds__(256) irfft_mean_kernel()
{
    __shared__ float2 tw[1024];
    __shared__ float2 Sb[NF];
    const int b = blockIdx.x;
    const int tid = threadIdx.x;
    for (int j = tid; j < 1024; j += 256) {
        float2 w = g_twG[j];
        tw[j] = make_float2(w.x, -w.y);
    }
    for (int j = tid; j < NF; j += 256) Sb[j] = g_S[b][j];
    __syncthreads();

    const int tau = blockIdx.y * 256 + tid;
    float acc = 0.f;
    #pragma unroll 4
    for (int j = 0; j < NF - 1; j++) {
        int id = ((F0 + j) * tau) & 1023;
        float2 s = Sb[j], w = tw[id];
        acc += s.x * w.x - s.y * w.y;
    }
    acc *= 2.0f;
    {
        int id = (512 * tau) & 1023;
        float2 s = Sb[NF - 1], w = tw[id];
        acc += s.x * w.x - s.y * w.y;
    }
    g_mv[b][tau] = acc * (1.0f / (1024.0f * 1024.0f));
}

// ---------------- global top-6 lags + per-batch softmax ---------------------
__global__ void __launch_bounds__(256) topk_kernel()
{
    __shared__ float g[1024];
    __shared__ float rv[256];
    __shared__ int   ri[256];
    __shared__ int   chosen[TOPK];
    const int tid = threadIdx.x;

    for (int t = tid; t < 1024; t += 256) {
        float s = 0.f;
        #pragma unroll
        for (int b = 0; b < BB; b++) s += g_mv[b][t];
        g[t] = s;
    }
    __syncthreads();

    for (int p = 0; p < TOPK; p++) {
        float best = -3.0e38f; int bi = 1 << 30;
        for (int t = tid; t < 1024; t += 256) {
            float v = g[t];
            if (v > best) { best = v; bi = t; }
        }
        rv[tid] = best; ri[tid] = bi;
        __syncthreads();
        for (int o = 128; o > 0; o >>= 1) {
            if (tid < o) {
                float v2 = rv[tid + o]; int i2 = ri[tid + o];
                if (v2 > rv[tid] || (v2 == rv[tid] && i2 < ri[tid])) {
                    rv[tid] = v2; ri[tid] = i2;
                }
            }
            __syncthreads();
        }
        if (tid == 0) { chosen[p] = ri[0]; g[ri[0]] = -3.0e38f; }
        __syncthreads();
    }

    if (tid < BB) {
        int b = tid;
        float w[TOPK], mx = -3.0e38f;
        #pragma unroll
        for (int i = 0; i < TOPK; i++) { w[i] = g_mv[b][chosen[i]]; mx = fmaxf(mx, w[i]); }
        float sum = 0.f;
        #pragma unroll
        for (int i = 0; i < TOPK; i++) { w[i] = expf(w[i] - mx); sum += w[i]; }
        #pragma unroll
        for (int i = 0; i < TOPK; i++) g_tc[b][i] = w[i] / sum;
    }
    if (tid >= 32 && tid < 32 + TOPK) g_idx[tid - 32] = chosen[tid - 32];
}

// ---------------- fused roll-gather + bias + residual + LayerNorm -----------
// out[b,t,:] = LN( sum_i w_i * hv[b,(t+idx_i)&1023,:] + bd + x[b,t,:] )
__global__ void __launch_bounds__(256) ln_gather_kernel(
    const float* __restrict__ x, const float* __restrict__ gamma,
    const float* __restrict__ beta, const float* __restrict__ bd,
    float* __restrict__ out)
{
    __shared__ int   sh[TOPK];
    __shared__ float w[TOPK];
    const int m = blockIdx.x;
    const int b = m >> 10, t = m & 1023;
    const int tid = threadIdx.x;
    if (tid < TOPK) { sh[tid] = g_idx[tid]; w[tid] = g_tc[b][tid]; }
    __syncthreads();

    const float* hp[TOPK];
    #pragma unroll
    for (int i = 0; i < TOPK; i++)
        hp[i] = g_hidden + ((size_t)((b << 10) | ((t + sh[i]) & 1023))) * 1024;
    const float* xi = x + (size_t)m * 1024;

    float v[4];
    float s1 = 0.f, s2 = 0.f;
    #pragma unroll
    for (int j = 0; j < 4; j++) {
        int c = tid + 256 * j;
        float acc = bd[c];
        #pragma unroll
        for (int i = 0; i < TOPK; i++) acc += w[i] * hp[i][c];
        acc += xi[c];
        v[j] = acc; s1 += acc; s2 += acc * acc;
    }
    #pragma unroll
    for (int o = 16; o > 0; o >>= 1) {
        s1 += __shfl_xor_sync(0xffffffffu, s1, o);
        s2 += __shfl_xor_sync(0xffffffffu, s2, o);
    }
    __shared__ float w1[8], w2[8];
    __shared__ float sh_mean, sh_inv;
    const int wid = tid >> 5, lane = tid & 31;
    if (lane == 0) { w1[wid] = s1; w2[wid] = s2; }
    __syncthreads();
    if (tid == 0) {
        float a = 0.f, bq = 0.f;
        #pragma unroll
        for (int i = 0; i < 8; i++) { a += w1[i]; bq += w2[i]; }
        float mean = a * (1.0f / 1024.0f);
        float var  = bq * (1.0f / 1024.0f) - mean * mean;
        sh_mean = mean;
        sh_inv  = rsqrtf(var + 1e-12f);
    }
    __syncthreads();
    const float mean = sh_mean, inv = sh_inv;
    #pragma unroll
    for (int j = 0; j < 4; j++) {
        int c = tid + 256 * j;
        out[(size_t)m * 1024 + c] = (v[j] - mean) * inv * gamma[c] + beta[c];
    }
}

// ---------------- launch ----------------------------------------------------
extern "C" void kernel_launch(void* const* d_in, const int* in_sizes, int n_in,
                              void* d_out, int out_size)
{
    (void)in_sizes; (void)n_in; (void)out_size;
    const float* x     = (const float*)d_in[0];
    const float* Wq    = (const float*)d_in[2];
    const float* bq    = (const float*)d_in[3];
    const float* Wk    = (const float*)d_in[4];
    const float* bk    = (const float*)d_in[5];
    const float* Wv    = (const float*)d_in[6];
    const float* bv    = (const float*)d_in[7];
    const float* Wd    = (const float*)d_in[8];
    const float* bd    = (const float*)d_in[9];
    const float* gamma = (const float*)d_in[10];
    const float* beta  = (const float*)d_in[11];
    float* out = (float*)d_out;

    static cudaStream_t s2 = nullptr;
    static cudaEvent_t ev0 = nullptr, evT = nullptr, evQK = nullptr, evD = nullptr;
    static bool attr_done = false;
    if (!attr_done) {
        cudaFuncSetAttribute(gemm_bf16, cudaFuncAttributeMaxDynamicSharedMemorySize, GSMEM);
        cudaStreamCreateWithFlags(&s2, cudaStreamNonBlocking);
        cudaEventCreateWithFlags(&ev0,  cudaEventDisableTiming);
        cudaEventCreateWithFlags(&evT,  cudaEventDisableTiming);
        cudaEventCreateWithFlags(&evQK, cudaEventDisableTiming);
        cudaEventCreateWithFlags(&evD,  cudaEventDisableTiming);
        attr_done = true;
    }

    // fork: twiddles + weight transpose on s2 concurrent with split_x on main
    cudaEventRecord(ev0, 0);
    cudaStreamWaitEvent(s2, ev0, 0);
    tw_init_kernel<<<4, 256, 0, s2>>>();
    transpose_w<<<dim3(32, 32, 4), 256, 0, s2>>>(Wq, Wk, Wv, Wd);
    split_x_kernel<<<NROW * LL / 1024, 256>>>(x);
    cudaEventRecord(evT, s2);
    cudaStreamWaitEvent(0, evT, 0);

    // Q,K GEMM on main stream
    gemm_bf16<<<dim3(8, 128, 2), 256, GSMEM>>>(bq, bk, bv, 0);
    cudaEventRecord(evQK, 0);

    // V -> hv chain on s2 (independent of the FFT chain)
    cudaStreamWaitEvent(s2, evQK, 0);
    gemm_bf16<<<dim3(8, 128, 1), 256, GSMEM, s2>>>(bq, bk, bv, 2);
    gemm_bf16<<<dim3(8, 128, 1), 256, GSMEM, s2>>>(bq, bk, bv, 3);
    cudaEventRecord(evD, s2);

    // FFT chain on main (small tail kernels overlap the big GEMMs on s2)
    fft_corr_kernel<<<NROW, 256>>>();
    reduce_S_kernel<<<dim3(BB, 77), 256>>>();
    irfft_mean_kernel<<<dim3(BB, 4), 256>>>();
    topk_kernel<<<1, 256>>>();

    // join: fused roll-gather + LN needs topk (main) and hv (s2)
    cudaStreamWaitEvent(0, evD, 0);
    ln_gather_kernel<<<NROW, 256>>>(x, gamma, beta, bd, out);
}

// round 16
// speedup vs baseline: 1.3889x; 1.1984x over previous
#include <cuda_runtime.h>
#include <cuda_bf16.h>
#include <cuda_fp16.h>
#include <cstdint>

// Problem constants
#define BB   16
#define LL   1024
#define HID  1024
#define NROW (BB * HID)
#define NF   308
#define F0   205
#define TOPK 6

// ---------------- scratch (device globals) ----------------------------------
__device__ float  g_q[NROW * LL];        // (B,HID,L)
__device__ float  g_k[NROW * LL];
__device__ float  g_hidden[NROW * LL];   // hv = v@Wd, (B*L, HID) row-major
__device__ __nv_bfloat16 g_x_hi[NROW * LL];    // x bf16 split (QK path)
__device__ __nv_bfloat16 g_x_lo[NROW * LL];
__device__ __half        g_x_h16[NROW * LL];   // x fp16 hi (V path)
__device__ __nv_bfloat16 g_wbf_hi[2 * HID * HID];  // Wq,Wk transposed [n][k]
__device__ __nv_bfloat16 g_wbf_lo[2 * HID * HID];
__device__ __half        g_wh_hi[2 * HID * HID];   // Wv,Wd transposed [n][k]
__device__ __half        g_wh_lo[2 * HID * HID];
__device__ __half        g_v_h16[NROW * LL];       // v (B*L, HID) fp16
__device__ float2 g_P[NROW * NF];
__device__ float2 g_S[BB][NF];
__device__ float  g_mv[BB][LL];
__device__ int    g_idx[TOPK];
__device__ float  g_tc[BB][TOPK];
__device__ float2 g_twG[1024];           // e^{-2*pi*i*j/1024}

// ---------------- twiddle init ----------------------------------------------
__global__ void __launch_bounds__(256) tw_init_kernel()
{
    int j = blockIdx.x * 256 + threadIdx.x;
    float s, c;
    sincospif(-(float)j / 512.0f, &s, &c);
    g_twG[j] = make_float2(c, s);
}

// ---------------- split helpers ---------------------------------------------
__device__ __forceinline__ void split_bf(float x, __nv_bfloat16& h, __nv_bfloat16& l) {
    h = __float2bfloat16(x);
    l = __float2bfloat16(x - __bfloat162float(h));
}
__device__ __forceinline__ void split_h(float x, __half& h, __half& l) {
    h = __float2half(x);
    l = __float2half(x - __half2float(h));
}

// x -> bf16 hi/lo (QK) + fp16 hi (V)
__global__ void __launch_bounds__(256) split_x_kernel(const float* __restrict__ x)
{
    size_t i = ((size_t)blockIdx.x * 256 + threadIdx.x) * 4;
    float4 v = *(const float4*)&x[i];
    __nv_bfloat16 h0, l0, h1, l1, h2, l2, h3, l3;
    split_bf(v.x, h0, l0); split_bf(v.y, h1, l1);
    split_bf(v.z, h2, l2); split_bf(v.w, h3, l3);
    __nv_bfloat162 hh01 = {h0, h1}, hh23 = {h2, h3};
    __nv_bfloat162 ll01 = {l0, l1}, ll23 = {l2, l3};
    uint2 hi, lo;
    hi.x = *(unsigned*)&hh01; hi.y = *(unsigned*)&hh23;
    lo.x = *(unsigned*)&ll01; lo.y = *(unsigned*)&ll23;
    *(uint2*)&g_x_hi[i] = hi;
    *(uint2*)&g_x_lo[i] = lo;
    __half2 f01 = __floats2half2_rn(v.x, v.y);
    __half2 f23 = __floats2half2_rn(v.z, v.w);
    uint2 f16;
    f16.x = *(unsigned*)&f01; f16.y = *(unsigned*)&f23;
    *(uint2*)&g_x_h16[i] = f16;
}

// ---------------- weight transpose + split ----------------------------------
// z=0,1 -> bf16 (Wq,Wk); z=2,3 -> fp16 (Wv,Wd)
__global__ void __launch_bounds__(256) transpose_w(
    const float* __restrict__ W0, const float* __restrict__ W1,
    const float* __restrict__ W2, const float* __restrict__ W3)
{
    __shared__ float tile[32][33];
    const int z = blockIdx.z;
    const float* src = (z == 0) ? W0 : (z == 1) ? W1 : (z == 2) ? W2 : W3;
    const int tx = threadIdx.x & 31, ty = threadIdx.x >> 5;   // 32 x 8
    const int x  = blockIdx.x * 32 + tx;
    const int y0 = blockIdx.y * 32;
    #pragma unroll
    for (int j = 0; j < 32; j += 8)
        tile[ty + j][tx] = src[(size_t)(y0 + ty + j) * HID + x];
    __syncthreads();
    const int x2 = y0 + tx;
    const int y2 = blockIdx.x * 32;
    if (z < 2) {
        __nv_bfloat16* dh = g_wbf_hi + (size_t)z * HID * HID;
        __nv_bfloat16* dl = g_wbf_lo + (size_t)z * HID * HID;
        #pragma unroll
        for (int j = 0; j < 32; j += 8) {
            float v = tile[tx][ty + j];
            __nv_bfloat16 h, l;
            split_bf(v, h, l);
            dh[(size_t)(y2 + ty + j) * HID + x2] = h;
            dl[(size_t)(y2 + ty + j) * HID + x2] = l;
        }
    } else {
        __half* dh = g_wh_hi + (size_t)(z - 2) * HID * HID;
        __half* dl = g_wh_lo + (size_t)(z - 2) * HID * HID;
        #pragma unroll
        for (int j = 0; j < 32; j += 8) {
            float v = tile[tx][ty + j];
            __half h, l;
            split_h(v, h, l);
            dh[(size_t)(y2 + ty + j) * HID + x2] = h;
            dl[(size_t)(y2 + ty + j) * HID + x2] = l;
        }
    }
}

// ---------------- common GEMM helpers ----------------------------------------
#define ARRB    8192                  // 128 * 64
#define STAGEB3 (3 * ARRB)            // f16 2-term stage (A_hi, B_hi, B_lo)
#define STAGEB4 (4 * ARRB)            // bf16 3-term stage
#define GSMEM4  (3 * STAGEB4)         // 98304
#define GSMEM3  (3 * STAGEB3)         // 73728

__device__ __forceinline__ void mma_bf16(float* c, const unsigned* a, const unsigned* b) {
    asm volatile(
        "mma.sync.aligned.m16n8k16.row.col.f32.bf16.bf16.f32 "
        "{%0,%1,%2,%3}, {%4,%5,%6,%7}, {%8,%9}, {%0,%1,%2,%3};"
        : "+f"(c[0]), "+f"(c[1]), "+f"(c[2]), "+f"(c[3])
        : "r"(a[0]), "r"(a[1]), "r"(a[2]), "r"(a[3]), "r"(b[0]), "r"(b[1]));
}
__device__ __forceinline__ void mma_f16(float* c, const unsigned* a, const unsigned* b) {
    asm volatile(
        "mma.sync.aligned.m16n8k16.row.col.f32.f16.f16.f32 "
        "{%0,%1,%2,%3}, {%4,%5,%6,%7}, {%8,%9}, {%0,%1,%2,%3};"
        : "+f"(c[0]), "+f"(c[1]), "+f"(c[2]), "+f"(c[3])
        : "r"(a[0]), "r"(a[1]), "r"(a[2]), "r"(a[3]), "r"(b[0]), "r"(b[1]));
}
__device__ __forceinline__ void ldsm4(unsigned* r, uint32_t addr) {
    asm volatile("ldmatrix.sync.aligned.m8n8.x4.shared.b16 {%0,%1,%2,%3}, [%4];"
        : "=r"(r[0]), "=r"(r[1]), "=r"(r[2]), "=r"(r[3]) : "r"(addr));
}
__device__ __forceinline__ void cpasync16(uint32_t dst, const void* src) {
    asm volatile("cp.async.cg.shared.global [%0], [%1], 16;" :: "r"(dst), "l"(src));
}

// ---------------- QK GEMM: bf16 3-term (unchanged math) ----------------------
__device__ __forceinline__ void issue_stage4(
    uint32_t sb,
    const __nv_bfloat16* __restrict__ Ah, const __nv_bfloat16* __restrict__ Al,
    const __nv_bfloat16* __restrict__ Bh, const __nv_bfloat16* __restrict__ Bl,
    int m0, int n0, int k0, int tid)
{
    #pragma unroll
    for (int c = 0; c < 2; c++) {
        int chunk = tid + c * 256;
        int row = chunk >> 2, ch = chunk & 3;
        uint32_t so = (uint32_t)row * 64 + (uint32_t)((ch ^ ((row >> 1) & 3)) << 4);
        size_t ga = (size_t)(m0 + row) * 1024 + k0 + ch * 8;
        size_t gb = (size_t)(n0 + row) * 1024 + k0 + ch * 8;
        cpasync16(sb + so,            Ah + ga);
        cpasync16(sb + ARRB + so,     Al + ga);
        cpasync16(sb + 2 * ARRB + so, Bh + gb);
        cpasync16(sb + 3 * ARRB + so, Bl + gb);
    }
}

__global__ void __launch_bounds__(256, 2) gemm_qk(
    const float* __restrict__ b0p, const float* __restrict__ b1p)
{
    extern __shared__ char smem[];
    const uint32_t sbase = (uint32_t)__cvta_generic_to_shared(smem);

    const int which = (int)blockIdx.z;      // 0=Q, 1=K
    const float* bias = (which == 0) ? b0p : b1p;
    const __nv_bfloat16* Ah = g_x_hi;
    const __nv_bfloat16* Al = g_x_lo;
    const __nv_bfloat16* Bh = g_wbf_hi + (size_t)which * HID * HID;
    const __nv_bfloat16* Bl = g_wbf_lo + (size_t)which * HID * HID;
    float* Out = (which == 0) ? g_q : g_k;

    const int m0 = blockIdx.y * 128;
    const int n0 = blockIdx.x * 128;
    const int tid  = threadIdx.x;
    const int lane = tid & 31;
    const int wid  = tid >> 5;
    const int wm = wid & 1;
    const int wn = wid >> 1;
    const int gid = lane >> 2;
    const int tig = lane & 3;

    const int a_rowb = wm * 64 + ((lane >> 3) & 1) * 8 + (lane & 7);
    const int a_cbit = (lane >> 4) & 1;
    const int b_rowb = wn * 32 + ((lane >> 4) & 1) * 8 + (lane & 7);
    const int b_cbit = (lane >> 3) & 1;

    uint32_t a_rb[4], b_rb[2];
    int a_swz[4], b_swz[2];
    #pragma unroll
    for (int mi = 0; mi < 4; mi++) {
        int r = a_rowb + mi * 16;
        a_rb[mi] = (uint32_t)r * 64;
        a_swz[mi] = (r >> 1) & 3;
    }
    #pragma unroll
    for (int pi = 0; pi < 2; pi++) {
        int r = b_rowb + pi * 16;
        b_rb[pi] = (uint32_t)r * 64;
        b_swz[pi] = (r >> 1) & 3;
    }

    float c[4][4][4];
    #pragma unroll
    for (int i = 0; i < 4; i++)
        #pragma unroll
        for (int j = 0; j < 4; j++)
            #pragma unroll
            for (int r = 0; r < 4; r++) c[i][j][r] = 0.f;

    issue_stage4(sbase + 0 * STAGEB4, Ah, Al, Bh, Bl, m0, n0, 0,  tid);
    asm volatile("cp.async.commit_group;");
    issue_stage4(sbase + 1 * STAGEB4, Ah, Al, Bh, Bl, m0, n0, 32, tid);
    asm volatile("cp.async.commit_group;");

    int buf = 0, nbuf = 2;
    for (int kt = 0; kt < 32; kt++) {
        asm volatile("cp.async.wait_group 1;");
        __syncthreads();

        if (kt + 2 < 32)
            issue_stage4(sbase + (uint32_t)nbuf * STAGEB4, Ah, Al, Bh, Bl,
                         m0, n0, (kt + 2) * 32, tid);
        asm volatile("cp.async.commit_group;");

        const uint32_t sb = sbase + (uint32_t)buf * STAGEB4;
        #pragma unroll
        for (int ks = 0; ks < 2; ks++) {
            unsigned ah[4][4], al[4][4], bh[4][2], bl[4][2];
            const int cbase = ks * 2;
            #pragma unroll
            for (int mi = 0; mi < 4; mi++) {
                uint32_t ad = sb + a_rb[mi]
                            + (uint32_t)((((cbase | a_cbit) ^ a_swz[mi]) << 4));
                ldsm4(ah[mi], ad);
                ldsm4(al[mi], ad + ARRB);
            }
            #pragma unroll
            for (int pi = 0; pi < 2; pi++) {
                uint32_t bd = sb + 2 * ARRB + b_rb[pi]
                            + (uint32_t)((((cbase | b_cbit) ^ b_swz[pi]) << 4));
                unsigned tmp[4];
                ldsm4(tmp, bd);
                bh[2 * pi][0] = tmp[0]; bh[2 * pi][1] = tmp[1];
                bh[2 * pi + 1][0] = tmp[2]; bh[2 * pi + 1][1] = tmp[3];
                ldsm4(tmp, bd + ARRB);
                bl[2 * pi][0] = tmp[0]; bl[2 * pi][1] = tmp[1];
                bl[2 * pi + 1][0] = tmp[2]; bl[2 * pi + 1][1] = tmp[3];
            }
            #pragma unroll
            for (int mi = 0; mi < 4; mi++)
                #pragma unroll
                for (int ni = 0; ni < 4; ni++) {
                    mma_bf16(c[mi][ni], ah[mi], bh[ni]);
                    mma_bf16(c[mi][ni], ah[mi], bl[ni]);
                    mma_bf16(c[mi][ni], al[mi], bh[ni]);
                }
        }
        buf = (buf == 2) ? 0 : buf + 1;
        nbuf = (nbuf == 2) ? 0 : nbuf + 1;
    }

    const int bidx = m0 >> 10;
    #pragma unroll
    for (int mi = 0; mi < 4; mi++) {
        #pragma unroll
        for (int r = 0; r < 2; r++) {
            int m = m0 + wm * 64 + mi * 16 + gid + r * 8;
            int t = m & 1023;
            #pragma unroll
            for (int ni = 0; ni < 4; ni++) {
                int nb = n0 + wn * 32 + ni * 8 + 2 * tig;
                float v0 = c[mi][ni][r * 2 + 0] + bias[nb];
                float v1 = c[mi][ni][r * 2 + 1] + bias[nb + 1];
                Out[(((size_t)(bidx << 10) + nb) << 10) + t] = v0;
                Out[(((size_t)(bidx << 10) + nb + 1) << 10) + t] = v1;
            }
        }
    }
}

// ---------------- V / hv GEMM: fp16 2-term (A-hi only, B hi+lo) --------------
__device__ __forceinline__ void issue_stage3(
    uint32_t sb,
    const __half* __restrict__ Ah,
    const __half* __restrict__ Bh, const __half* __restrict__ Bl,
    int m0, int n0, int k0, int tid)
{
    #pragma unroll
    for (int c = 0; c < 2; c++) {
        int chunk = tid + c * 256;
        int row = chunk >> 2, ch = chunk & 3;
        uint32_t so = (uint32_t)row * 64 + (uint32_t)((ch ^ ((row >> 1) & 3)) << 4);
        size_t ga = (size_t)(m0 + row) * 1024 + k0 + ch * 8;
        size_t gb = (size_t)(n0 + row) * 1024 + k0 + ch * 8;
        cpasync16(sb + so,            Ah + ga);
        cpasync16(sb + ARRB + so,     Bh + gb);
        cpasync16(sb + 2 * ARRB + so, Bl + gb);
    }
}

// mode 2: v = x@Wv + bv -> fp16 rows; mode 3: hv = v@Wd -> fp32 rows (no bias)
__global__ void __launch_bounds__(256, 2) gemm_f16(
    const float* __restrict__ bias, int mode)
{
    extern __shared__ char smem[];
    const uint32_t sbase = (uint32_t)__cvta_generic_to_shared(smem);

    const __half* Ah = (mode == 3) ? g_v_h16 : g_x_h16;
    const __half* Bh = g_wh_hi + (size_t)(mode - 2) * HID * HID;
    const __half* Bl = g_wh_lo + (size_t)(mode - 2) * HID * HID;

    const int m0 = blockIdx.y * 128;
    const int n0 = blockIdx.x * 128;
    const int tid  = threadIdx.x;
    const int lane = tid & 31;
    const int wid  = tid >> 5;
    const int wm = wid & 1;
    const int wn = wid >> 1;
    const int gid = lane >> 2;
    const int tig = lane & 3;

    const int a_rowb = wm * 64 + ((lane >> 3) & 1) * 8 + (lane & 7);
    const int a_cbit = (lane >> 4) & 1;
    const int b_rowb = wn * 32 + ((lane >> 4) & 1) * 8 + (lane & 7);
    const int b_cbit = (lane >> 3) & 1;

    uint32_t a_rb[4], b_rb[2];
    int a_swz[4], b_swz[2];
    #pragma unroll
    for (int mi = 0; mi < 4; mi++) {
        int r = a_rowb + mi * 16;
        a_rb[mi] = (uint32_t)r * 64;
        a_swz[mi] = (r >> 1) & 3;
    }
    #pragma unroll
    for (int pi = 0; pi < 2; pi++) {
        int r = b_rowb + pi * 16;
        b_rb[pi] = (uint32_t)r * 64;
        b_swz[pi] = (r >> 1) & 3;
    }

    float c[4][4][4];
    #pragma unroll
    for (int i = 0; i < 4; i++)
        #pragma unroll
        for (int j = 0; j < 4; j++)
            #pragma unroll
            for (int r = 0; r < 4; r++) c[i][j][r] = 0.f;

    issue_stage3(sbase + 0 * STAGEB3, Ah, Bh, Bl, m0, n0, 0,  tid);
    asm volatile("cp.async.commit_group;");
    issue_stage3(sbase + 1 * STAGEB3, Ah, Bh, Bl, m0, n0, 32, tid);
    asm volatile("cp.async.commit_group;");

    int buf = 0, nbuf = 2;
    for (int kt = 0; kt < 32; kt++) {
        asm volatile("cp.async.wait_group 1;");
        __syncthreads();

        if (kt + 2 < 32)
            issue_stage3(sbase + (uint32_t)nbuf * STAGEB3, Ah, Bh, Bl,
                         m0, n0, (kt + 2) * 32, tid);
        asm volatile("cp.async.commit_group;");

        const uint32_t sb = sbase + (uint32_t)buf * STAGEB3;
        #pragma unroll
        for (int ks = 0; ks < 2; ks++) {
            unsigned ah[4][4], bh[4][2], bl[4][2];
            const int cbase = ks * 2;
            #pragma unroll
            for (int mi = 0; mi < 4; mi++) {
                uint32_t ad = sb + a_rb[mi]
                            + (uint32_t)((((cbase | a_cbit) ^ a_swz[mi]) << 4));
                ldsm4(ah[mi], ad);
            }
            #pragma unroll
            for (int pi = 0; pi < 2; pi++) {
                uint32_t bd = sb + ARRB + b_rb[pi]
                            + (uint32_t)((((cbase | b_cbit) ^ b_swz[pi]) << 4));
                unsigned tmp[4];
                ldsm4(tmp, bd);
                bh[2 * pi][0] = tmp[0]; bh[2 * pi][1] = tmp[1];
                bh[2 * pi + 1][0] = tmp[2]; bh[2 * pi + 1][1] = tmp[3];
                ldsm4(tmp, bd + ARRB);
                bl[2 * pi][0] = tmp[0]; bl[2 * pi][1] = tmp[1];
                bl[2 * pi + 1][0] = tmp[2]; bl[2 * pi + 1][1] = tmp[3];
            }
            #pragma unroll
            for (int mi = 0; mi < 4; mi++)
                #pragma unroll
                for (int ni = 0; ni < 4; ni++) {
                    mma_f16(c[mi][ni], ah[mi], bh[ni]);
                    mma_f16(c[mi][ni], ah[mi], bl[ni]);
                }
        }
        buf = (buf == 2) ? 0 : buf + 1;
        nbuf = (nbuf == 2) ? 0 : nbuf + 1;
    }

    if (mode == 2) {
        #pragma unroll
        for (int mi = 0; mi < 4; mi++) {
            #pragma unroll
            for (int r = 0; r < 2; r++) {
                int m = m0 + wm * 64 + mi * 16 + gid + r * 8;
                #pragma unroll
                for (int ni = 0; ni < 4; ni++) {
                    int nb = n0 + wn * 32 + ni * 8 + 2 * tig;
                    float v0 = c[mi][ni][r * 2 + 0] + bias[nb];
                    float v1 = c[mi][ni][r * 2 + 1] + bias[nb + 1];
                    __half2 hv = __floats2half2_rn(v0, v1);
                    *(__half2*)&g_v_h16[(size_t)m * 1024 + nb] = hv;
                }
            }
        }
    } else {
        #pragma unroll
        for (int mi = 0; mi < 4; mi++) {
            #pragma unroll
            for (int r = 0; r < 2; r++) {
                int m = m0 + wm * 64 + mi * 16 + gid + r * 8;
                #pragma unroll
                for (int ni = 0; ni < 4; ni++) {
                    int nb = n0 + wn * 32 + ni * 8 + 2 * tig;
                    float2 v;
                    v.x = c[mi][ni][r * 2 + 0];
                    v.y = c[mi][ni][r * 2 + 1];
                    *(float2*)&g_hidden[(size_t)m * 1024 + nb] = v;
                }
            }
        }
    }
}

// ---------------- radix-4 DIF FFT + cross spectrum --------------------------
__device__ __forceinline__ int fswz(int p) { return p ^ ((p >> 2) & 15); }
__device__ __forceinline__ int rev4(int x) {
    return ((x & 3) << 8) | (((x >> 2) & 3) << 6) | (((x >> 4) & 3) << 4)
         | (((x >> 6) & 3) << 2) | ((x >> 8) & 3);
}
__device__ __forceinline__ float2 cmul(float2 a, float2 w) {
    return make_float2(a.x * w.x - a.y * w.y, a.x * w.y + a.y * w.x);
}

__global__ void __launch_bounds__(256) fft_corr_kernel()
{
    __shared__ float2 Zs[1024];
    __shared__ float2 tw[1024];
    const int row = blockIdx.x;
    const int t = threadIdx.x;
    const float* qr = g_q + (size_t)row * 1024;
    const float* kr = g_k + (size_t)row * 1024;

    for (int j = t; j < 1024; j += 256) tw[j] = g_twG[j];
    __syncthreads();

    {
        float2 x0 = make_float2(qr[t],       kr[t]);
        float2 x1 = make_float2(qr[t + 256], kr[t + 256]);
        float2 x2 = make_float2(qr[t + 512], kr[t + 512]);
        float2 x3 = make_float2(qr[t + 768], kr[t + 768]);
        float2 p02 = make_float2(x0.x + x2.x, x0.y + x2.y);
        float2 m02 = make_float2(x0.x - x2.x, x0.y - x2.y);
        float2 p13 = make_float2(x1.x + x3.x, x1.y + x3.y);
        float2 m13 = make_float2(x1.x - x3.x, x1.y - x3.y);
        float2 y0 = make_float2(p02.x + p13.x, p02.y + p13.y);
        float2 y2 = make_float2(p02.x - p13.x, p02.y - p13.y);
        float2 y1 = make_float2(m02.x + m13.y, m02.y - m13.x);
        float2 y3 = make_float2(m02.x - m13.y, m02.y + m13.x);
        int e = t;
        Zs[fswz(t)]       = y0;
        Zs[fswz(t + 256)] = cmul(y1, tw[e]);
        Zs[fswz(t + 512)] = cmul(y2, tw[2 * e]);
        Zs[fswz(t + 768)] = cmul(y3, tw[3 * e]);
    }
    __syncthreads();

    #pragma unroll
    for (int s = 1; s < 5; s++) {
        const int qsh = 8 - 2 * s;
        const int quarter = 1 << qsh;
        const int j = t & (quarter - 1);
        const int i0 = ((t >> qsh) << (qsh + 2)) + j;
        const int e = j << (2 * s);
        float2 x0 = Zs[fswz(i0)];
        float2 x1 = Zs[fswz(i0 + quarter)];
        float2 x2 = Zs[fswz(i0 + 2 * quarter)];
        float2 x3 = Zs[fswz(i0 + 3 * quarter)];
        float2 p02 = make_float2(x0.x + x2.x, x0.y + x2.y);
        float2 m02 = make_float2(x0.x - x2.x, x0.y - x2.y);
        float2 p13 = make_float2(x1.x + x3.x, x1.y + x3.y);
        float2 m13 = make_float2(x1.x - x3.x, x1.y - x3.y);
        float2 y0 = make_float2(p02.x + p13.x, p02.y + p13.y);
        float2 y2 = make_float2(p02.x - p13.x, p02.y - p13.y);
        float2 y1 = make_float2(m02.x + m13.y, m02.y - m13.x);
        float2 y3 = make_float2(m02.x - m13.y, m02.y + m13.x);
        __syncthreads();
        Zs[fswz(i0)]               = y0;
        Zs[fswz(i0 + quarter)]     = cmul(y1, tw[e]);
        Zs[fswz(i0 + 2 * quarter)] = cmul(y2, tw[2 * e]);
        Zs[fswz(i0 + 3 * quarter)] = cmul(y3, tw[3 * e]);
        __syncthreads();
    }

    for (int f = F0 + t; f <= 512; f += 256) {
        float2 A  = Zs[fswz(rev4(f))];
        float2 Zc = Zs[fswz(rev4(1024 - f))];
        float Br =  Zc.x, Bi = -Zc.y;
        float Ur = A.x + Br, Ui = A.y + Bi;
        float Vr = A.x - Br, Vi = A.y - Bi;
        float Pr = 0.25f * (Ur * Vi - Ui * Vr);
        float Pi = 0.25f * (Ur * Vr + Ui * Vi);
        g_P[(size_t)row * NF + (f - F0)] = make_float2(Pr, Pi);
    }
}

// ---------------- deterministic channel reduction (coalesced) ---------------
__global__ void __launch_bounds__(256) reduce_S_kernel()
{
    const int b = blockIdx.x;
    const int tid = threadIdx.x;
    const int j = blockIdx.y * 4 + (tid & 3);
    float2 acc = make_float2(0.f, 0.f);
    for (int r = tid >> 2; r < 1024; r += 64) {
        float2 p = g_P[(size_t)((b << 10) + r) * NF + j];
        acc.x += p.x; acc.y += p.y;
    }
    __shared__ float2 sh[256];
    sh[tid] = acc;
    __syncthreads();
    for (int o = 128; o >= 4; o >>= 1) {
        if (tid < o) { sh[tid].x += sh[tid + o].x; sh[tid].y += sh[tid + o].y; }
        __syncthreads();
    }
    if (tid < 4) g_S[b][blockIdx.y * 4 + tid] = sh[tid];
}

// ---------------- irfft of masked spectrum -> mean_value --------------------
__global__ void __launch_bounds__(256) irfft_mean_kernel()
{
    __shared__ float2 tw[1024];
    __shared__ float2 Sb[NF];
    const int b = blockIdx.x;
    const int tid = threadIdx.x;
    for (int j = tid; j < 1024; j += 256) {
        float2 w = g_twG[j];
        tw[j] = make_float2(w.x, -w.y);
    }
    for (int j = tid; j < NF; j += 256) Sb[j] = g_S[b][j];
    __syncthreads();

    const int tau = blockIdx.y * 256 + tid;
    float acc = 0.f;
    #pragma unroll 4
    for (int j = 0; j < NF - 1; j++) {
        int id = ((F0 + j) * tau) & 1023;
        float2 s = Sb[j], w = tw[id];
        acc += s.x * w.x - s.y * w.y;
    }
    acc *= 2.0f;
    {
        int id = (512 * tau) & 1023;
        float2 s = Sb[NF - 1], w = tw[id];
        acc += s.x * w.x - s.y * w.y;
    }
    g_mv[b][tau] = acc * (1.0f / (1024.0f * 1024.0f));
}

// ---------------- global top-6 lags + per-batch softmax ---------------------
__global__ void __launch_bounds__(256) topk_kernel()
{
    __shared__ float g[1024];
    __shared__ float rv[256];
    __shared__ int   ri[256];
    __shared__ int   chosen[TOPK];
    const int tid = threadIdx.x;

    for (int t = tid; t < 1024; t += 256) {
        float s = 0.f;
        #pragma unroll
        for (int b = 0; b < BB; b++) s += g_mv[b][t];
        g[t] = s;
    }
    __syncthreads();

    for (int p = 0; p < TOPK; p++) {
        float best = -3.0e38f; int bi = 1 << 30;
        for (int t = tid; t < 1024; t += 256) {
            float v = g[t];
            if (v > best) { best = v; bi = t; }
        }
        rv[tid] = best; ri[tid] = bi;
        __syncthreads();
        for (int o = 128; o > 0; o >>= 1) {
            if (tid < o) {
                float v2 = rv[tid + o]; int i2 = ri[tid + o];
                if (v2 > rv[tid] || (v2 == rv[tid] && i2 < ri[tid])) {
                    rv[tid] = v2; ri[tid] = i2;
                }
            }
            __syncthreads();
        }
        if (tid == 0) { chosen[p] = ri[0]; g[ri[0]] = -3.0e38f; }
        __syncthreads();
    }

    if (tid < BB) {
        int b = tid;
        float w[TOPK], mx = -3.0e38f;
        #pragma unroll
        for (int i = 0; i < TOPK; i++) { w[i] = g_mv[b][chosen[i]]; mx = fmaxf(mx, w[i]); }
        float sum = 0.f;
        #pragma unroll
        for (int i = 0; i < TOPK; i++) { w[i] = expf(w[i] - mx); sum += w[i]; }
        #pragma unroll
        for (int i = 0; i < TOPK; i++) g_tc[b][i] = w[i] / sum;
    }
    if (tid >= 32 && tid < 32 + TOPK) g_idx[tid - 32] = chosen[tid - 32];
}

// ---------------- fused roll-gather + bias + residual + LayerNorm -----------
__global__ void __launch_bounds__(256) ln_gather_kernel(
    const float* __restrict__ x, const float* __restrict__ gamma,
    const float* __restrict__ beta, const float* __restrict__ bd,
    float* __restrict__ out)
{
    __shared__ int   sh[TOPK];
    __shared__ float w[TOPK];
    const int m = blockIdx.x;
    const int b = m >> 10, t = m & 1023;
    const int tid = threadIdx.x;
    if (tid < TOPK) { sh[tid] = g_idx[tid]; w[tid] = g_tc[b][tid]; }
    __syncthreads();

    const float* hp[TOPK];
    #pragma unroll
    for (int i = 0; i < TOPK; i++)
        hp[i] = g_hidden + ((size_t)((b << 10) | ((t + sh[i]) & 1023))) * 1024;
    const float* xi = x + (size_t)m * 1024;

    float v[4];
    float s1 = 0.f, s2 = 0.f;
    #pragma unroll
    for (int j = 0; j < 4; j++) {
        int c = tid + 256 * j;
        float acc = bd[c];
        #pragma unroll
        for (int i = 0; i < TOPK; i++) acc += w[i] * hp[i][c];
        acc += xi[c];
        v[j] = acc; s1 += acc; s2 += acc * acc;
    }
    #pragma unroll
    for (int o = 16; o > 0; o >>= 1) {
        s1 += __shfl_xor_sync(0xffffffffu, s1, o);
        s2 += __shfl_xor_sync(0xffffffffu, s2, o);
    }
    __shared__ float w1[8], w2[8];
    __shared__ float sh_mean, sh_inv;
    const int wid = tid >> 5, lane = tid & 31;
    if (lane == 0) { w1[wid] = s1; w2[wid] = s2; }
    __syncthreads();
    if (tid == 0) {
        float a = 0.f, bq = 0.f;
        #pragma unroll
        for (int i = 0; i < 8; i++) { a += w1[i]; bq += w2[i]; }
        float mean = a * (1.0f / 1024.0f);
        float var  = bq * (1.0f / 1024.0f) - mean * mean;
        sh_mean = mean;
        sh_inv  = rsqrtf(var + 1e-12f);
    }
    __syncthreads();
    const float mean = sh_mean, inv = sh_inv;
    #pragma unroll
    for (int j = 0; j < 4; j++) {
        int c = tid + 256 * j;
        out[(size_t)m * 1024 + c] = (v[j] - mean) * inv * gamma[c] + beta[c];
    }
}

// ---------------- launch ----------------------------------------------------
extern "C" void kernel_launch(void* const* d_in, const int* in_sizes, int n_in,
                              void* d_out, int out_size)
{
    (void)in_sizes; (void)n_in; (void)out_size;
    const float* x     = (const float*)d_in[0];
    const float* Wq    = (const float*)d_in[2];
    const float* bq    = (const float*)d_in[3];
    const float* Wk    = (const float*)d_in[4];
    const float* bk    = (const float*)d_in[5];
    const float* Wv    = (const float*)d_in[6];
    const float* bv    = (const float*)d_in[7];
    const float* Wd    = (const float*)d_in[8];
    const float* bd    = (const float*)d_in[9];
    const float* gamma = (const float*)d_in[10];
    const float* beta  = (const float*)d_in[11];
    float* out = (float*)d_out;

    static cudaStream_t s2 = nullptr;
    static cudaEvent_t ev0 = nullptr, evT = nullptr, evQK = nullptr, evD = nullptr;
    static bool attr_done = false;
    if (!attr_done) {
        cudaFuncSetAttribute(gemm_qk,  cudaFuncAttributeMaxDynamicSharedMemorySize, GSMEM4);
        cudaFuncSetAttribute(gemm_f16, cudaFuncAttributeMaxDynamicSharedMemorySize, GSMEM3);
        cudaStreamCreateWithFlags(&s2, cudaStreamNonBlocking);
        cudaEventCreateWithFlags(&ev0,  cudaEventDisableTiming);
        cudaEventCreateWithFlags(&evT,  cudaEventDisableTiming);
        cudaEventCreateWithFlags(&evQK, cudaEventDisableTiming);
        cudaEventCreateWithFlags(&evD,  cudaEventDisableTiming);
        attr_done = true;
    }

    // fork: twiddles + weight transpose on s2 concurrent with split_x on main
    cudaEventRecord(ev0, 0);
    cudaStreamWaitEvent(s2, ev0, 0);
    tw_init_kernel<<<4, 256, 0, s2>>>();
    transpose_w<<<dim3(32, 32, 4), 256, 0, s2>>>(Wq, Wk, Wv, Wd);
    split_x_kernel<<<NROW * LL / 1024, 256>>>(x);
    cudaEventRecord(evT, s2);
    cudaStreamWaitEvent(0, evT, 0);

    // Q,K GEMM (bf16 3-term) on main stream
    gemm_qk<<<dim3(8, 128, 2), 256, GSMEM4>>>(bq, bk);
    cudaEventRecord(evQK, 0);

    // V -> hv chain (fp16 2-term) on s2, overlapping the FFT chain
    cudaStreamWaitEvent(s2, evQK, 0);
    gemm_f16<<<dim3(8, 128, 1), 256, GSMEM3, s2>>>(bv, 2);
    gemm_f16<<<dim3(8, 128, 1), 256, GSMEM3, s2>>>(bv, 3);
    cudaEventRecord(evD, s2);

    // FFT chain on main
    fft_corr_kernel<<<NROW, 256>>>();
    reduce_S_kernel<<<dim3(BB, 77), 256>>>();
    irfft_mean_kernel<<<dim3(BB, 4), 256>>>();
    topk_kernel<<<1, 256>>>();

    // join: fused roll-gather + LN needs topk (main) and hv (s2)
    cudaStreamWaitEvent(0, evD, 0);
    ln_gather_kernel<<<NROW, 256>>>(x, gamma, beta, bd, out);
}

// round 17
// speedup vs baseline: 1.9908x; 1.4334x over previous
#include <cuda_runtime.h>
#include <cuda_bf16.h>
#include <cuda_fp16.h>
#include <cstdint>

// Problem constants
#define BB   16
#define LL   1024
#define HID  1024
#define NROW (BB * HID)
#define NF   308
#define F0   205
#define TOPK 6
#define MROWS (BB * NF * 2)       // 9856 = 77 * 128

// ---------------- scratch (device globals) ----------------------------------
__device__ float  g_xT[NROW * LL];       // x transposed: (B, HID, L)
__device__ float  g_hidden[NROW * LL];   // hv = v@Wd, (B*L, HID) row-major
__device__ __half g_x_h16[NROW * LL];    // x fp16 (V path)
__device__ __half g_wh_hi[2 * HID * HID];   // Wv,Wd transposed [n][k] fp16 split
__device__ __half g_wh_lo[2 * HID * HID];
__device__ __half g_v_h16[NROW * LL];    // v (B*L, HID) fp16
__device__ __nv_bfloat16 g_wq_hi[HID * HID];   // Wq bf16 split (orig layout)
__device__ __nv_bfloat16 g_wq_lo[HID * HID];
__device__ __nv_bfloat16 g_wk_hi[HID * HID];
__device__ __nv_bfloat16 g_wk_lo[HID * HID];
__device__ __nv_bfloat16 g_M_hi[HID * HID];    // M = Wq@Wk^T, [d][e]
__device__ __nv_bfloat16 g_M_lo[HID * HID];
__device__ __nv_bfloat16 g_Xp_hi[(size_t)MROWS * HID];  // X^(f) rows: m=(b,f,reim), k=e
__device__ __nv_bfloat16 g_Xp_lo[(size_t)MROWS * HID];
__device__ float  g_Y[(size_t)MROWS * HID];    // Y rows [m][d]
__device__ float2 g_S[BB][NF];
__device__ float  g_mv[BB][LL];
__device__ int    g_idx[TOPK];
__device__ float  g_tc[BB][TOPK];
__device__ float2 g_twG[1024];           // e^{-2*pi*i*j/1024}

// ---------------- twiddle init ----------------------------------------------
__global__ void __launch_bounds__(256) tw_init_kernel()
{
    int j = blockIdx.x * 256 + threadIdx.x;
    float s, c;
    sincospif(-(float)j / 512.0f, &s, &c);
    g_twG[j] = make_float2(c, s);
}

// ---------------- split helpers ---------------------------------------------
__device__ __forceinline__ void split_bf(float x, __nv_bfloat16& h, __nv_bfloat16& l) {
    h = __float2bfloat16(x);
    l = __float2bfloat16(x - __bfloat162float(h));
}
__device__ __forceinline__ void split_h(float x, __half& h, __half& l) {
    h = __float2half(x);
    l = __float2half(x - __half2float(h));
}

// x -> fp16 (V path only)
__global__ void __launch_bounds__(256) split_x16_kernel(const float* __restrict__ x)
{
    size_t i = ((size_t)blockIdx.x * 256 + threadIdx.x) * 4;
    float4 v = *(const float4*)&x[i];
    __half2 f01 = __floats2half2_rn(v.x, v.y);
    __half2 f23 = __floats2half2_rn(v.z, v.w);
    uint2 f16;
    f16.x = *(unsigned*)&f01; f16.y = *(unsigned*)&f23;
    *(uint2*)&g_x_h16[i] = f16;
}

// Wq,Wk -> bf16 hi/lo in ORIGINAL layout (for M = Wq@Wk^T, contraction over c)
__global__ void __launch_bounds__(256) split_wqk_kernel(
    const float* __restrict__ Wq, const float* __restrict__ Wk)
{
    const float* src = (blockIdx.y == 0) ? Wq : Wk;
    __nv_bfloat16* dh = (blockIdx.y == 0) ? g_wq_hi : g_wk_hi;
    __nv_bfloat16* dl = (blockIdx.y == 0) ? g_wq_lo : g_wk_lo;
    size_t i = ((size_t)blockIdx.x * 256 + threadIdx.x) * 4;
    float4 v = *(const float4*)&src[i];
    __nv_bfloat16 h0, l0, h1, l1, h2, l2, h3, l3;
    split_bf(v.x, h0, l0); split_bf(v.y, h1, l1);
    split_bf(v.z, h2, l2); split_bf(v.w, h3, l3);
    __nv_bfloat162 hh01 = {h0, h1}, hh23 = {h2, h3};
    __nv_bfloat162 ll01 = {l0, l1}, ll23 = {l2, l3};
    uint2 hi, lo;
    hi.x = *(unsigned*)&hh01; hi.y = *(unsigned*)&hh23;
    lo.x = *(unsigned*)&ll01; lo.y = *(unsigned*)&ll23;
    *(uint2*)&dh[i] = hi;
    *(uint2*)&dl[i] = lo;
}

// x (B,L,HID) -> xT (B,HID,L) fp32
__global__ void __launch_bounds__(256) transpose_x_kernel(const float* __restrict__ x)
{
    __shared__ float tile[32][33];
    const int b = blockIdx.z;
    const int tx = threadIdx.x & 31, ty = threadIdx.x >> 5;   // 32 x 8
    const int d0 = blockIdx.x * 32;
    const int t0 = blockIdx.y * 32;
    #pragma unroll
    for (int j = 0; j < 32; j += 8)
        tile[ty + j][tx] = x[(((size_t)(b << 10)) + t0 + ty + j) * 1024 + d0 + tx];
    __syncthreads();
    #pragma unroll
    for (int j = 0; j < 32; j += 8)
        g_xT[(((size_t)(b << 10)) + d0 + ty + j) * 1024 + t0 + tx] = tile[tx][ty + j];
}

// Wv,Wd transpose + fp16 split
__global__ void __launch_bounds__(256) transpose_wvd(
    const float* __restrict__ W0, const float* __restrict__ W1)
{
    __shared__ float tile[32][33];
    const int z = blockIdx.z;
    const float* src = (z == 0) ? W0 : W1;
    __half* dh = g_wh_hi + (size_t)z * HID * HID;
    __half* dl = g_wh_lo + (size_t)z * HID * HID;
    const int tx = threadIdx.x & 31, ty = threadIdx.x >> 5;
    const int x  = blockIdx.x * 32 + tx;
    const int y0 = blockIdx.y * 32;
    #pragma unroll
    for (int j = 0; j < 32; j += 8)
        tile[ty + j][tx] = src[(size_t)(y0 + ty + j) * HID + x];
    __syncthreads();
    const int x2 = y0 + tx;
    const int y2 = blockIdx.x * 32;
    #pragma unroll
    for (int j = 0; j < 32; j += 8) {
        float v = tile[tx][ty + j];
        __half h, l;
        split_h(v, h, l);
        dh[(size_t)(y2 + ty + j) * HID + x2] = h;
        dl[(size_t)(y2 + ty + j) * HID + x2] = l;
    }
}

// ---------------- common GEMM helpers ----------------------------------------
#define ARRB    8192                  // 128 * 64
#define STAGEB3 (3 * ARRB)
#define STAGEB4 (4 * ARRB)
#define GSMEM4  (3 * STAGEB4)         // 98304
#define GSMEM3  (3 * STAGEB3)         // 73728

__device__ __forceinline__ void mma_bf16(float* c, const unsigned* a, const unsigned* b) {
    asm volatile(
        "mma.sync.aligned.m16n8k16.row.col.f32.bf16.bf16.f32 "
        "{%0,%1,%2,%3}, {%4,%5,%6,%7}, {%8,%9}, {%0,%1,%2,%3};"
        : "+f"(c[0]), "+f"(c[1]), "+f"(c[2]), "+f"(c[3])
        : "r"(a[0]), "r"(a[1]), "r"(a[2]), "r"(a[3]), "r"(b[0]), "r"(b[1]));
}
__device__ __forceinline__ void mma_f16(float* c, const unsigned* a, const unsigned* b) {
    asm volatile(
        "mma.sync.aligned.m16n8k16.row.col.f32.f16.f16.f32 "
        "{%0,%1,%2,%3}, {%4,%5,%6,%7}, {%8,%9}, {%0,%1,%2,%3};"
        : "+f"(c[0]), "+f"(c[1]), "+f"(c[2]), "+f"(c[3])
        : "r"(a[0]), "r"(a[1]), "r"(a[2]), "r"(a[3]), "r"(b[0]), "r"(b[1]));
}
__device__ __forceinline__ void ldsm4(unsigned* r, uint32_t addr) {
    asm volatile("ldmatrix.sync.aligned.m8n8.x4.shared.b16 {%0,%1,%2,%3}, [%4];"
        : "=r"(r[0]), "=r"(r[1]), "=r"(r[2]), "=r"(r[3]) : "r"(addr));
}
__device__ __forceinline__ void cpasync16(uint32_t dst, const void* src) {
    asm volatile("cp.async.cg.shared.global [%0], [%1], 16;" :: "r"(dst), "l"(src));
}

// ---------------- bf16 3-term GEMM (M and Y) ---------------------------------
__device__ __forceinline__ void issue_stage4(
    uint32_t sb,
    const __nv_bfloat16* __restrict__ Ah, const __nv_bfloat16* __restrict__ Al,
    const __nv_bfloat16* __restrict__ Bh, const __nv_bfloat16* __restrict__ Bl,
    int m0, int n0, int k0, int tid)
{
    #pragma unroll
    for (int c = 0; c < 2; c++) {
        int chunk = tid + c * 256;
        int row = chunk >> 2, ch = chunk & 3;
        uint32_t so = (uint32_t)row * 64 + (uint32_t)((ch ^ ((row >> 1) & 3)) << 4);
        size_t ga = (size_t)(m0 + row) * 1024 + k0 + ch * 8;
        size_t gb = (size_t)(n0 + row) * 1024 + k0 + ch * 8;
        cpasync16(sb + so,            Ah + ga);
        cpasync16(sb + ARRB + so,     Al + ga);
        cpasync16(sb + 2 * ARRB + so, Bh + gb);
        cpasync16(sb + 3 * ARRB + so, Bl + gb);
    }
}

// mode 0: M = Wq@Wk^T -> bf16 split; mode 1: Y = Xp@M^T-rows -> fp32
__global__ void __launch_bounds__(256, 2) gemm_bf3(int mode)
{
    extern __shared__ char smem[];
    const uint32_t sbase = (uint32_t)__cvta_generic_to_shared(smem);

    const __nv_bfloat16* Ah = (mode == 0) ? g_wq_hi : g_Xp_hi;
    const __nv_bfloat16* Al = (mode == 0) ? g_wq_lo : g_Xp_lo;
    const __nv_bfloat16* Bh = (mode == 0) ? g_wk_hi : g_M_hi;
    const __nv_bfloat16* Bl = (mode == 0) ? g_wk_lo : g_M_lo;

    const int m0 = blockIdx.y * 128;
    const int n0 = blockIdx.x * 128;
    const int tid  = threadIdx.x;
    const int lane = tid & 31;
    const int wid  = tid >> 5;
    const int wm = wid & 1;
    const int wn = wid >> 1;
    const int gid = lane >> 2;
    const int tig = lane & 3;

    const int a_rowb = wm * 64 + ((lane >> 3) & 1) * 8 + (lane & 7);
    const int a_cbit = (lane >> 4) & 1;
    const int b_rowb = wn * 32 + ((lane >> 4) & 1) * 8 + (lane & 7);
    const int b_cbit = (lane >> 3) & 1;

    uint32_t a_rb[4], b_rb[2];
    int a_swz[4], b_swz[2];
    #pragma unroll
    for (int mi = 0; mi < 4; mi++) {
        int r = a_rowb + mi * 16;
        a_rb[mi] = (uint32_t)r * 64;
        a_swz[mi] = (r >> 1) & 3;
    }
    #pragma unroll
    for (int pi = 0; pi < 2; pi++) {
        int r = b_rowb + pi * 16;
        b_rb[pi] = (uint32_t)r * 64;
        b_swz[pi] = (r >> 1) & 3;
    }

    float c[4][4][4];
    #pragma unroll
    for (int i = 0; i < 4; i++)
        #pragma unroll
        for (int j = 0; j < 4; j++)
            #pragma unroll
            for (int r = 0; r < 4; r++) c[i][j][r] = 0.f;

    issue_stage4(sbase + 0 * STAGEB4, Ah, Al, Bh, Bl, m0, n0, 0,  tid);
    asm volatile("cp.async.commit_group;");
    issue_stage4(sbase + 1 * STAGEB4, Ah, Al, Bh, Bl, m0, n0, 32, tid);
    asm volatile("cp.async.commit_group;");

    int buf = 0, nbuf = 2;
    for (int kt = 0; kt < 32; kt++) {
        asm volatile("cp.async.wait_group 1;");
        __syncthreads();

        if (kt + 2 < 32)
            issue_stage4(sbase + (uint32_t)nbuf * STAGEB4, Ah, Al, Bh, Bl,
                         m0, n0, (kt + 2) * 32, tid);
        asm volatile("cp.async.commit_group;");

        const uint32_t sb = sbase + (uint32_t)buf * STAGEB4;
        #pragma unroll
        for (int ks = 0; ks < 2; ks++) {
            unsigned ah[4][4], al[4][4], bh[4][2], bl[4][2];
            const int cbase = ks * 2;
            #pragma unroll
            for (int mi = 0; mi < 4; mi++) {
                uint32_t ad = sb + a_rb[mi]
                            + (uint32_t)((((cbase | a_cbit) ^ a_swz[mi]) << 4));
                ldsm4(ah[mi], ad);
                ldsm4(al[mi], ad + ARRB);
            }
            #pragma unroll
            for (int pi = 0; pi < 2; pi++) {
                uint32_t bd = sb + 2 * ARRB + b_rb[pi]
                            + (uint32_t)((((cbase | b_cbit) ^ b_swz[pi]) << 4));
                unsigned tmp[4];
                ldsm4(tmp, bd);
                bh[2 * pi][0] = tmp[0]; bh[2 * pi][1] = tmp[1];
                bh[2 * pi + 1][0] = tmp[2]; bh[2 * pi + 1][1] = tmp[3];
                ldsm4(tmp, bd + ARRB);
                bl[2 * pi][0] = tmp[0]; bl[2 * pi][1] = tmp[1];
                bl[2 * pi + 1][0] = tmp[2]; bl[2 * pi + 1][1] = tmp[3];
            }
            #pragma unroll
            for (int mi = 0; mi < 4; mi++)
                #pragma unroll
                for (int ni = 0; ni < 4; ni++) {
                    mma_bf16(c[mi][ni], ah[mi], bh[ni]);
                    mma_bf16(c[mi][ni], ah[mi], bl[ni]);
                    mma_bf16(c[mi][ni], al[mi], bh[ni]);
                }
        }
        buf = (buf == 2) ? 0 : buf + 1;
        nbuf = (nbuf == 2) ? 0 : nbuf + 1;
    }

    if (mode == 0) {
        #pragma unroll
        for (int mi = 0; mi < 4; mi++) {
            #pragma unroll
            for (int r = 0; r < 2; r++) {
                int m = m0 + wm * 64 + mi * 16 + gid + r * 8;
                #pragma unroll
                for (int ni = 0; ni < 4; ni++) {
                    int nb = n0 + wn * 32 + ni * 8 + 2 * tig;
                    __nv_bfloat16 h0, l0, h1, l1;
                    split_bf(c[mi][ni][r * 2 + 0], h0, l0);
                    split_bf(c[mi][ni][r * 2 + 1], h1, l1);
                    __nv_bfloat162 hh = {h0, h1}, ll = {l0, l1};
                    *(__nv_bfloat162*)&g_M_hi[(size_t)m * 1024 + nb] = hh;
                    *(__nv_bfloat162*)&g_M_lo[(size_t)m * 1024 + nb] = ll;
                }
            }
        }
    } else {
        #pragma unroll
        for (int mi = 0; mi < 4; mi++) {
            #pragma unroll
            for (int r = 0; r < 2; r++) {
                int m = m0 + wm * 64 + mi * 16 + gid + r * 8;
                #pragma unroll
                for (int ni = 0; ni < 4; ni++) {
                    int nb = n0 + wn * 32 + ni * 8 + 2 * tig;
                    float2 v;
                    v.x = c[mi][ni][r * 2 + 0];
                    v.y = c[mi][ni][r * 2 + 1];
                    *(float2*)&g_Y[(size_t)m * 1024 + nb] = v;
                }
            }
        }
    }
}

// ---------------- V / hv GEMM: fp16 2-term (unchanged) -----------------------
__device__ __forceinline__ void issue_stage3(
    uint32_t sb,
    const __half* __restrict__ Ah,
    const __half* __restrict__ Bh, const __half* __restrict__ Bl,
    int m0, int n0, int k0, int tid)
{
    #pragma unroll
    for (int c = 0; c < 2; c++) {
        int chunk = tid + c * 256;
        int row = chunk >> 2, ch = chunk & 3;
        uint32_t so = (uint32_t)row * 64 + (uint32_t)((ch ^ ((row >> 1) & 3)) << 4);
        size_t ga = (size_t)(m0 + row) * 1024 + k0 + ch * 8;
        size_t gb = (size_t)(n0 + row) * 1024 + k0 + ch * 8;
        cpasync16(sb + so,            Ah + ga);
        cpasync16(sb + ARRB + so,     Bh + gb);
        cpasync16(sb + 2 * ARRB + so, Bl + gb);
    }
}

__global__ void __launch_bounds__(256, 2) gemm_f16(
    const float* __restrict__ bias, int mode)
{
    extern __shared__ char smem[];
    const uint32_t sbase = (uint32_t)__cvta_generic_to_shared(smem);

    const __half* Ah = (mode == 3) ? g_v_h16 : g_x_h16;
    const __half* Bh = g_wh_hi + (size_t)(mode - 2) * HID * HID;
    const __half* Bl = g_wh_lo + (size_t)(mode - 2) * HID * HID;

    const int m0 = blockIdx.y * 128;
    const int n0 = blockIdx.x * 128;
    const int tid  = threadIdx.x;
    const int lane = tid & 31;
    const int wid  = tid >> 5;
    const int wm = wid & 1;
    const int wn = wid >> 1;
    const int gid = lane >> 2;
    const int tig = lane & 3;

    const int a_rowb = wm * 64 + ((lane >> 3) & 1) * 8 + (lane & 7);
    const int a_cbit = (lane >> 4) & 1;
    const int b_rowb = wn * 32 + ((lane >> 4) & 1) * 8 + (lane & 7);
    const int b_cbit = (lane >> 3) & 1;

    uint32_t a_rb[4], b_rb[2];
    int a_swz[4], b_swz[2];
    #pragma unroll
    for (int mi = 0; mi < 4; mi++) {
        int r = a_rowb + mi * 16;
        a_rb[mi] = (uint32_t)r * 64;
        a_swz[mi] = (r >> 1) & 3;
    }
    #pragma unroll
    for (int pi = 0; pi < 2; pi++) {
        int r = b_rowb + pi * 16;
        b_rb[pi] = (uint32_t)r * 64;
        b_swz[pi] = (r >> 1) & 3;
    }

    float c[4][4][4];
    #pragma unroll
    for (int i = 0; i < 4; i++)
        #pragma unroll
        for (int j = 0; j < 4; j++)
            #pragma unroll
            for (int r = 0; r < 4; r++) c[i][j][r] = 0.f;

    issue_stage3(sbase + 0 * STAGEB3, Ah, Bh, Bl, m0, n0, 0,  tid);
    asm volatile("cp.async.commit_group;");
    issue_stage3(sbase + 1 * STAGEB3, Ah, Bh, Bl, m0, n0, 32, tid);
    asm volatile("cp.async.commit_group;");

    int buf = 0, nbuf = 2;
    for (int kt = 0; kt < 32; kt++) {
        asm volatile("cp.async.wait_group 1;");
        __syncthreads();

        if (kt + 2 < 32)
            issue_stage3(sbase + (uint32_t)nbuf * STAGEB3, Ah, Bh, Bl,
                         m0, n0, (kt + 2) * 32, tid);
        asm volatile("cp.async.commit_group;");

        const uint32_t sb = sbase + (uint32_t)buf * STAGEB3;
        #pragma unroll
        for (int ks = 0; ks < 2; ks++) {
            unsigned ah[4][4], bh[4][2], bl[4][2];
            const int cbase = ks * 2;
            #pragma unroll
            for (int mi = 0; mi < 4; mi++) {
                uint32_t ad = sb + a_rb[mi]
                            + (uint32_t)((((cbase | a_cbit) ^ a_swz[mi]) << 4));
                ldsm4(ah[mi], ad);
            }
            #pragma unroll
            for (int pi = 0; pi < 2; pi++) {
                uint32_t bd = sb + ARRB + b_rb[pi]
                            + (uint32_t)((((cbase | b_cbit) ^ b_swz[pi]) << 4));
                unsigned tmp[4];
                ldsm4(tmp, bd);
                bh[2 * pi][0] = tmp[0]; bh[2 * pi][1] = tmp[1];
                bh[2 * pi + 1][0] = tmp[2]; bh[2 * pi + 1][1] = tmp[3];
                ldsm4(tmp, bd + ARRB);
                bl[2 * pi][0] = tmp[0]; bl[2 * pi][1] = tmp[1];
                bl[2 * pi + 1][0] = tmp[2]; bl[2 * pi + 1][1] = tmp[3];
            }
            #pragma unroll
            for (int mi = 0; mi < 4; mi++)
                #pragma unroll
                for (int ni = 0; ni < 4; ni++) {
                    mma_f16(c[mi][ni], ah[mi], bh[ni]);
                    mma_f16(c[mi][ni], ah[mi], bl[ni]);
                }
        }
        buf = (buf == 2) ? 0 : buf + 1;
        nbuf = (nbuf == 2) ? 0 : nbuf + 1;
    }

    if (mode == 2) {
        #pragma unroll
        for (int mi = 0; mi < 4; mi++) {
            #pragma unroll
            for (int r = 0; r < 2; r++) {
                int m = m0 + wm * 64 + mi * 16 + gid + r * 8;
                #pragma unroll
                for (int ni = 0; ni < 4; ni++) {
                    int nb = n0 + wn * 32 + ni * 8 + 2 * tig;
                    float v0 = c[mi][ni][r * 2 + 0] + bias[nb];
                    float v1 = c[mi][ni][r * 2 + 1] + bias[nb + 1];
                    __half2 hv = __floats2half2_rn(v0, v1);
                    *(__half2*)&g_v_h16[(size_t)m * 1024 + nb] = hv;
                }
            }
        }
    } else {
        #pragma unroll
        for (int mi = 0; mi < 4; mi++) {
            #pragma unroll
            for (int r = 0; r < 2; r++) {
                int m = m0 + wm * 64 + mi * 16 + gid + r * 8;
                #pragma unroll
                for (int ni = 0; ni < 4; ni++) {
                    int nb = n0 + wn * 32 + ni * 8 + 2 * tig;
                    float2 v;
                    v.x = c[mi][ni][r * 2 + 0];
                    v.y = c[mi][ni][r * 2 + 1];
                    *(float2*)&g_hidden[(size_t)m * 1024 + nb] = v;
                }
            }
        }
    }
}

// ---------------- FFT of x: 8 channels per block, band output bf16-split -----
__device__ __forceinline__ int fswz(int p) { return p ^ ((p >> 2) & 15); }
__device__ __forceinline__ int rev4(int x) {
    return ((x & 3) << 8) | (((x >> 2) & 3) << 6) | (((x >> 4) & 3) << 4)
         | (((x >> 6) & 3) << 2) | ((x >> 8) & 3);
}
__device__ __forceinline__ float2 cmul(float2 a, float2 w) {
    return make_float2(a.x * w.x - a.y * w.y, a.x * w.y + a.y * w.x);
}

__global__ void __launch_bounds__(256) fftX_kernel()
{
    __shared__ float2 Zs[1024];
    __shared__ float2 tw[1024];
    __shared__ __nv_bfloat162 ob[NF][2][2][4];   // [fi][reim][hilo][pair]
    const int b = blockIdx.y;
    const int g = blockIdx.x;                    // channels [8g, 8g+8)
    const int t = threadIdx.x;

    for (int j = t; j < 1024; j += 256) tw[j] = g_twG[j];

    for (int p = 0; p < 4; p++) {
        const float* r0 = g_xT + ((size_t)(b << 10) + g * 8 + 2 * p) * 1024;
        const float* r1 = r0 + 1024;
        float2 x0 = make_float2(r0[t],       r1[t]);
        float2 x1 = make_float2(r0[t + 256], r1[t + 256]);
        float2 x2 = make_float2(r0[t + 512], r1[t + 512]);
        float2 x3 = make_float2(r0[t + 768], r1[t + 768]);
        __syncthreads();      // tw ready (p=0) / prev extraction done (p>0)
        {
            float2 p02 = make_float2(x0.x + x2.x, x0.y + x2.y);
            float2 m02 = make_float2(x0.x - x2.x, x0.y - x2.y);
            float2 p13 = make_float2(x1.x + x3.x, x1.y + x3.y);
            float2 m13 = make_float2(x1.x - x3.x, x1.y - x3.y);
            float2 y0 = make_float2(p02.x + p13.x, p02.y + p13.y);
            float2 y2 = make_float2(p02.x - p13.x, p02.y - p13.y);
            float2 y1 = make_float2(m02.x + m13.y, m02.y - m13.x);
            float2 y3 = make_float2(m02.x - m13.y, m02.y + m13.x);
            Zs[fswz(t)]       = y0;
            Zs[fswz(t + 256)] = cmul(y1, tw[t]);
            Zs[fswz(t + 512)] = cmul(y2, tw[2 * t]);
            Zs[fswz(t + 768)] = cmul(y3, tw[3 * t]);
        }
        __syncthreads();
        #pragma unroll
        for (int s = 1; s < 5; s++) {
            const int qsh = 8 - 2 * s;
            const int quarter = 1 << qsh;
            const int j = t & (quarter - 1);
            const int i0 = ((t >> qsh) << (qsh + 2)) + j;
            const int e = j << (2 * s);
            float2 z0 = Zs[fswz(i0)];
            float2 z1 = Zs[fswz(i0 + quarter)];
            float2 z2 = Zs[fswz(i0 + 2 * quarter)];
            float2 z3 = Zs[fswz(i0 + 3 * quarter)];
            float2 p02 = make_float2(z0.x + z2.x, z0.y + z2.y);
            float2 m02 = make_float2(z0.x - z2.x, z0.y - z2.y);
            float2 p13 = make_float2(z1.x + z3.x, z1.y + z3.y);
            float2 m13 = make_float2(z1.x - z3.x, z1.y - z3.y);
            float2 y0 = make_float2(p02.x + p13.x, p02.y + p13.y);
            float2 y2 = make_float2(p02.x - p13.x, p02.y - p13.y);
            float2 y1 = make_float2(m02.x + m13.y, m02.y - m13.x);
            float2 y3 = make_float2(m02.x - m13.y, m02.y + m13.x);
            __syncthreads();
            Zs[fswz(i0)]               = y0;
            Zs[fswz(i0 + quarter)]     = cmul(y1, tw[e]);
            Zs[fswz(i0 + 2 * quarter)] = cmul(y2, tw[2 * e]);
            Zs[fswz(i0 + 3 * quarter)] = cmul(y3, tw[3 * e]);
            __syncthreads();
        }
        // extract band, 2-for-1 unpack, bf16 split into smem out-buffer
        for (int f = F0 + t; f <= 512; f += 256) {
            float2 a  = Zs[fswz(rev4(f))];
            float2 bz = Zs[fswz(rev4(1024 - f))];
            float X0r = 0.5f * (a.x + bz.x), X0i = 0.5f * (a.y - bz.y);  // ch e=2p
            float X1r = 0.5f * (a.y + bz.y), X1i = 0.5f * (bz.x - a.x);  // ch e=2p+1
            int fi = f - F0;
            __nv_bfloat16 h0, l0, h1, l1;
            split_bf(X0r, h0, l0); split_bf(X1r, h1, l1);
            ob[fi][0][0][p] = {h0, h1};
            ob[fi][0][1][p] = {l0, l1};
            split_bf(X0i, h0, l0); split_bf(X1i, h1, l1);
            ob[fi][1][0][p] = {h0, h1};
            ob[fi][1][1][p] = {l0, l1};
        }
    }
    __syncthreads();
    // coalesced 16B writes: row m = (b*NF+fi)*2+reim, cols [8g, 8g+8)
    for (int idx = t; idx < NF * 4; idx += 256) {
        int fi = idx >> 2, rh = idx & 3, reim = rh >> 1, hilo = rh & 1;
        size_t m = ((size_t)b * NF + fi) * 2 + reim;
        __nv_bfloat16* dst = (hilo ? g_Xp_lo : g_Xp_hi) + m * 1024 + g * 8;
        *(uint4*)dst = *(uint4*)&ob[fi][reim][hilo][0];
    }
}

// ---------------- S[b][f] = sum_d X^_d * conj(Y_d) combine -------------------
__global__ void __launch_bounds__(128) sdot_kernel()
{
    const int bf = blockIdx.x;             // b*NF + fi
    const int tid = threadIdx.x;
    const size_t m = (size_t)bf * 2;
    const __nv_bfloat16* xh0 = g_Xp_hi + m * 1024;         // Re X^
    const __nv_bfloat16* xl0 = g_Xp_lo + m * 1024;
    const __nv_bfloat16* xh1 = xh0 + 1024;                 // Im X^
    const __nv_bfloat16* xl1 = xl0 + 1024;
    const float* yr = g_Y + m * 1024;                      // Re V
    const float* yi = yr + 1024;                           // Im V
    float sr = 0.f, si = 0.f;
    for (int d = tid; d < 1024; d += 128) {
        float Xr = __bfloat162float(xh0[d]) + __bfloat162float(xl0[d]);
        float Xi = __bfloat162float(xh1[d]) + __bfloat162float(xl1[d]);
        float Vr = yr[d], Vi = yi[d];
        sr += Xr * Vr + Xi * Vi;           // Re(X * conj(V))
        si += Xi * Vr - Xr * Vi;           // Im(X * conj(V))
    }
    __shared__ float shr[128], shi[128];
    shr[tid] = sr; shi[tid] = si;
    __syncthreads();
    for (int o = 64; o > 0; o >>= 1) {
        if (tid < o) { shr[tid] += shr[tid + o]; shi[tid] += shi[tid + o]; }
        __syncthreads();
    }
    if (tid == 0) g_S[bf / NF][bf % NF] = make_float2(shr[0], shi[0]);
}

// ---------------- irfft of masked spectrum -> mean_value --------------------
__global__ void __launch_bounds__(256) irfft_mean_kernel()
{
    __shared__ float2 tw[1024];
    __shared__ float2 Sb[NF];
    const int b = blockIdx.x;
    const int tid = threadIdx.x;
    for (int j = tid; j < 1024; j += 256) {
        float2 w = g_twG[j];
        tw[j] = make_float2(w.x, -w.y);
    }
    for (int j = tid; j < NF; j += 256) Sb[j] = g_S[b][j];
    __syncthreads();

    const int tau = blockIdx.y * 256 + tid;
    float acc = 0.f;
    #pragma unroll 4
    for (int j = 0; j < NF - 1; j++) {
        int id = ((F0 + j) * tau) & 1023;
        float2 s = Sb[j], w = tw[id];
        acc += s.x * w.x - s.y * w.y;
    }
    acc *= 2.0f;
    {
        int id = (512 * tau) & 1023;
        float2 s = Sb[NF - 1], w = tw[id];
        acc += s.x * w.x - s.y * w.y;
    }
    g_mv[b][tau] = acc * (1.0f / (1024.0f * 1024.0f));
}

// ---------------- global top-6 lags + per-batch softmax ---------------------
__global__ void __launch_bounds__(256) topk_kernel()
{
    __shared__ float g[1024];
    __shared__ float rv[256];
    __shared__ int   ri[256];
    __shared__ int   chosen[TOPK];
    const int tid = threadIdx.x;

    for (int t = tid; t < 1024; t += 256) {
        float s = 0.f;
        #pragma unroll
        for (int b = 0; b < BB; b++) s += g_mv[b][t];
        g[t] = s;
    }
    __syncthreads();

    for (int p = 0; p < TOPK; p++) {
        float best = -3.0e38f; int bi = 1 << 30;
        for (int t = tid; t < 1024; t += 256) {
            float v = g[t];
            if (v > best) { best = v; bi = t; }
        }
        rv[tid] = best; ri[tid] = bi;
        __syncthreads();
        for (int o = 128; o > 0; o >>= 1) {
            if (tid < o) {
                float v2 = rv[tid + o]; int i2 = ri[tid + o];
                if (v2 > rv[tid] || (v2 == rv[tid] && i2 < ri[tid])) {
                    rv[tid] = v2; ri[tid] = i2;
                }
            }
            __syncthreads();
        }
        if (tid == 0) { chosen[p] = ri[0]; g[ri[0]] = -3.0e38f; }
        __syncthreads();
    }

    if (tid < BB) {
        int b = tid;
        float w[TOPK], mx = -3.0e38f;
        #pragma unroll
        for (int i = 0; i < TOPK; i++) { w[i] = g_mv[b][chosen[i]]; mx = fmaxf(mx, w[i]); }
        float sum = 0.f;
        #pragma unroll
        for (int i = 0; i < TOPK; i++) { w[i] = expf(w[i] - mx); sum += w[i]; }
        #pragma unroll
        for (int i = 0; i < TOPK; i++) g_tc[b][i] = w[i] / sum;
    }
    if (tid >= 32 && tid < 32 + TOPK) g_idx[tid - 32] = chosen[tid - 32];
}

// ---------------- fused roll-gather + bias + residual + LayerNorm -----------
__global__ void __launch_bounds__(256) ln_gather_kernel(
    const float* __restrict__ x, const float* __restrict__ gamma,
    const float* __restrict__ beta, const float* __restrict__ bd,
    float* __restrict__ out)
{
    __shared__ int   sh[TOPK];
    __shared__ float w[TOPK];
    const int m = blockIdx.x;
    const int b = m >> 10, t = m & 1023;
    const int tid = threadIdx.x;
    if (tid < TOPK) { sh[tid] = g_idx[tid]; w[tid] = g_tc[b][tid]; }
    __syncthreads();

    const float* hp[TOPK];
    #pragma unroll
    for (int i = 0; i < TOPK; i++)
        hp[i] = g_hidden + ((size_t)((b << 10) | ((t + sh[i]) & 1023))) * 1024;
    const float* xi = x + (size_t)m * 1024;

    float v[4];
    float s1 = 0.f, s2 = 0.f;
    #pragma unroll
    for (int j = 0; j < 4; j++) {
        int c = tid + 256 * j;
        float acc = bd[c];
        #pragma unroll
        for (int i = 0; i < TOPK; i++) acc += w[i] * hp[i][c];
        acc += xi[c];
        v[j] = acc; s1 += acc; s2 += acc * acc;
    }
    #pragma unroll
    for (int o = 16; o > 0; o >>= 1) {
        s1 += __shfl_xor_sync(0xffffffffu, s1, o);
        s2 += __shfl_xor_sync(0xffffffffu, s2, o);
    }
    __shared__ float w1[8], w2[8];
    __shared__ float sh_mean, sh_inv;
    const int wid = tid >> 5, lane = tid & 31;
    if (lane == 0) { w1[wid] = s1; w2[wid] = s2; }
    __syncthreads();
    if (tid == 0) {
        float a = 0.f, bq = 0.f;
        #pragma unroll
        for (int i = 0; i < 8; i++) { a += w1[i]; bq += w2[i]; }
        float mean = a * (1.0f / 1024.0f);
        float var  = bq * (1.0f / 1024.0f) - mean * mean;
        sh_mean = mean;
        sh_inv  = rsqrtf(var + 1e-12f);
    }
    __syncthreads();
    const float mean = sh_mean, inv = sh_inv;
    #pragma unroll
    for (int j = 0; j < 4; j++) {
        int c = tid + 256 * j;
        out[(size_t)m * 1024 + c] = (v[j] - mean) * inv * gamma[c] + beta[c];
    }
}

// ---------------- launch ----------------------------------------------------
extern "C" void kernel_launch(void* const* d_in, const int* in_sizes, int n_in,
                              void* d_out, int out_size)
{
    (void)in_sizes; (void)n_in; (void)out_size;
    const float* x     = (const float*)d_in[0];
    const float* Wq    = (const float*)d_in[2];
    const float* Wk    = (const float*)d_in[4];
    const float* Wv    = (const float*)d_in[6];
    const float* bv    = (const float*)d_in[7];
    const float* Wd    = (const float*)d_in[8];
    const float* bd    = (const float*)d_in[9];
    const float* gamma = (const float*)d_in[10];
    const float* beta  = (const float*)d_in[11];
    float* out = (float*)d_out;

    static cudaStream_t s2 = nullptr;
    static cudaEvent_t ev0 = nullptr, evM = nullptr, evD = nullptr;
    static bool attr_done = false;
    if (!attr_done) {
        cudaFuncSetAttribute(gemm_bf3, cudaFuncAttributeMaxDynamicSharedMemorySize, GSMEM4);
        cudaFuncSetAttribute(gemm_f16, cudaFuncAttributeMaxDynamicSharedMemorySize, GSMEM3);
        cudaStreamCreateWithFlags(&s2, cudaStreamNonBlocking);
        cudaEventCreateWithFlags(&ev0, cudaEventDisableTiming);
        cudaEventCreateWithFlags(&evM, cudaEventDisableTiming);
        cudaEventCreateWithFlags(&evD, cudaEventDisableTiming);
        attr_done = true;
    }

    cudaEventRecord(ev0, 0);
    cudaStreamWaitEvent(s2, ev0, 0);

    // s2: V-path prep + M GEMM, then V -> hv fp16 chain
    split_x16_kernel<<<NROW * LL / 1024, 256, 0, s2>>>(x);
    transpose_wvd<<<dim3(32, 32, 2), 256, 0, s2>>>(Wv, Wd);
    split_wqk_kernel<<<dim3(1024, 2), 256, 0, s2>>>(Wq, Wk);
    gemm_bf3<<<dim3(8, 8), 256, GSMEM4, s2>>>(0);                 // M = Wq@Wk^T
    cudaEventRecord(evM, s2);
    gemm_f16<<<dim3(8, 128), 256, GSMEM3, s2>>>(bv, 2);           // v
    gemm_f16<<<dim3(8, 128), 256, GSMEM3, s2>>>(bv, 3);           // hv = v@Wd
    cudaEventRecord(evD, s2);

    // main: x transpose -> FFT of x -> Y GEMM -> S -> irfft -> topk
    tw_init_kernel<<<4, 256>>>();
    transpose_x_kernel<<<dim3(32, 32, 16), 256>>>(x);
    fftX_kernel<<<dim3(128, 16), 256>>>();
    cudaStreamWaitEvent(0, evM, 0);
    gemm_bf3<<<dim3(8, 77), 256, GSMEM4>>>(1);                    // Y = Xp @ M
    sdot_kernel<<<BB * NF, 128>>>();
    irfft_mean_kernel<<<dim3(BB, 4), 256>>>();
    topk_kernel<<<1, 256>>>();

    // join: fused roll-gather + LN needs topk (main) and hv (s2)
    cudaStreamWaitEvent(0, evD, 0);
    ln_gather_kernel<<<NROW, 256>>>(x, gamma, beta, bd, out);
}